// round 1
// baseline (speedup 1.0000x reference)
#include <cuda_runtime.h>
#include <math.h>

#define BB 128
#define NN 100
#define HH 128
#define NODES (BB*NN)          // 12800
#define PI_F 3.14159265358979323846f
#define EPS_F 1e-7f

// Scratch (allocation-free rule: device globals)
__device__ float g_R[NODES * 9];
__device__ float g_cv[NODES * 3];
__device__ float g_hacc[NODES * HH];

__device__ __forceinline__ void vel_to_R(float vx, float vy, float vz, float* R) {
    float rho = sqrtf(vx * vx + vy * vy + vz * vz);
    float theta = atan2f(vy, vx);
    if (theta < 0.0f) theta += 2.0f * PI_F;   // mirror reference numerics
    float c = vz / (rho + EPS_F);
    c = fminf(fmaxf(c, -1.0f), 1.0f);
    float phi = acosf(c);
    float st, ct, sp, cp;
    sincosf(theta, &st, &ct);
    sincosf(phi, &sp, &cp);
    R[0] = cp * ct; R[1] = -st;  R[2] = sp * ct;
    R[3] = cp * st; R[4] = ct;   R[5] = sp * st;
    R[6] = -sp;     R[7] = 0.0f; R[8] = cp;
}

// ---------------------------------------------------------------------------
// Kernel 1: per-node rotation matrix + canonical velocity
// ---------------------------------------------------------------------------
__global__ void node_pre_kernel(const float* __restrict__ inp) {
    int idx = blockIdx.x * 128 + threadIdx.x;
    if (idx >= NODES) return;
    const float* v = inp + (size_t)idx * 6 + 3;
    float vx = v[0], vy = v[1], vz = v[2];
    float R[9];
    vel_to_R(vx, vy, vz, R);
#pragma unroll
    for (int i = 0; i < 9; i++) g_R[idx * 9 + i] = R[i];
    // canon_vel = R^T v
    g_cv[idx * 3 + 0] = R[0] * vx + R[3] * vy + R[6] * vz;
    g_cv[idx * 3 + 1] = R[1] * vx + R[4] * vy + R[7] * vz;
    g_cv[idx * 3 + 2] = R[2] * vx + R[5] * vy + R[8] * vz;
}

// ---------------------------------------------------------------------------
// Kernel 2: per (b, recv) block. Threads 0..98 build the 12 varying edge
// features; all 128 threads then accumulate  hacc[t] = sum_e silu(ea_e @ W1)_t
// with the per-node constant part of edge_attr (zeros + canon_vel) folded
// into 'base'. The W2 GEMM is deferred to kernel 3 (linearity of the sum).
// ---------------------------------------------------------------------------
__global__ __launch_bounds__(128) void edge_agg_kernel(
    const float* __restrict__ inp,
    const float* __restrict__ W1,
    const float* __restrict__ b1)
{
    __shared__ __align__(16) float ea[NN - 1][12];
    int b = blockIdx.x / NN;
    int r = blockIdx.x % NN;
    int t = threadIdx.x;
    int node_r = b * NN + r;

    // W1 column for this thread's hidden channel (varying rows 0..11)
    float w1c[12];
#pragma unroll
    for (int k = 0; k < 12; k++) w1c[k] = W1[k * HH + t];

    float cv0 = g_cv[node_r * 3 + 0];
    float cv1 = g_cv[node_r * 3 + 1];
    float cv2 = g_cv[node_r * 3 + 2];
    // rows 12..14 multiply exact zeros; rows 15..17 multiply canon_vel(recv)
    float base = b1[t] + cv0 * W1[15 * HH + t] + cv1 * W1[16 * HH + t]
                       + cv2 * W1[17 * HH + t];

    if (t < NN - 1) {
        int s = t + (t >= r ? 1 : 0);
        int node_s = b * NN + s;
        const float* xj = inp + (size_t)node_s * 6;
        const float* xi = inp + (size_t)node_r * 6;
        float Rr[9], Rs[9];
#pragma unroll
        for (int i = 0; i < 9; i++) { Rr[i] = g_R[node_r * 9 + i]; Rs[i] = g_R[node_s * 9 + i]; }

        float rel0 = xj[0] - xi[0], rel1 = xj[1] - xi[1], rel2 = xj[2] - xi[2];
        // rot_rel = Rr^T rel
        float rr0 = Rr[0] * rel0 + Rr[3] * rel1 + Rr[6] * rel2;
        float rr1 = Rr[1] * rel0 + Rr[4] * rel1 + Rr[7] * rel2;
        float rr2 = Rr[2] * rel0 + Rr[5] * rel1 + Rr[8] * rel2;
        // rot_or = Rr^T @ Rs (only 5 entries needed)
        float ro00 = Rr[0] * Rs[0] + Rr[3] * Rs[3] + Rr[6] * Rs[6];
        float ro10 = Rr[1] * Rs[0] + Rr[4] * Rs[3] + Rr[7] * Rs[6];
        float ro20 = Rr[2] * Rs[0] + Rr[5] * Rs[3] + Rr[8] * Rs[6];
        float ro21 = Rr[2] * Rs[1] + Rr[5] * Rs[4] + Rr[8] * Rs[7];
        float ro22 = Rr[2] * Rs[2] + Rr[5] * Rs[5] + Rr[8] * Rs[8];

        float e0 = atan2f(ro10, ro00) / PI_F;
        float sa = fminf(fmaxf(-ro20, -1.0f), 1.0f);
        float e1 = asinf(sa) / PI_F;
        float e2 = atan2f(ro21, ro22) / PI_F;
        float dist  = sqrtf(rel0 * rel0 + rel1 * rel1 + rel2 * rel2);
        float rho_e = sqrtf(rr0 * rr0 + rr1 * rr1 + rr2 * rr2);
        float th = atan2f(rr1, rr0);
        float cc = rr2 / (rho_e + EPS_F);
        cc = fminf(fmaxf(cc, -1.0f), 1.0f);
        float ph = acosf(cc);
        float vj0 = xj[3], vj1 = xj[4], vj2 = xj[5];
        float rv0 = Rr[0] * vj0 + Rr[3] * vj1 + Rr[6] * vj2;
        float rv1 = Rr[1] * vj0 + Rr[4] * vj1 + Rr[7] * vj2;
        float rv2 = Rr[2] * vj0 + Rr[5] * vj1 + Rr[8] * vj2;

        ea[t][0] = rr0;  ea[t][1] = rr1;  ea[t][2] = rr2;
        ea[t][3] = e0;   ea[t][4] = e1;   ea[t][5] = e2;
        ea[t][6] = dist; ea[t][7] = th;   ea[t][8] = ph;
        ea[t][9] = rv0;  ea[t][10] = rv1; ea[t][11] = rv2;
    }
    __syncthreads();

    float acc0 = 0.0f, acc1 = 0.0f, acc2 = 0.0f;
#pragma unroll 1
    for (int i = 0; i < (NN - 1) / 3; i++) {
#pragma unroll
        for (int u = 0; u < 3; u++) {
            const float* e = ea[i * 3 + u];
            float4 p0 = *(const float4*)(e);
            float4 p1 = *(const float4*)(e + 4);
            float4 p2 = *(const float4*)(e + 8);
            float a = base;
            a += p0.x * w1c[0] + p0.y * w1c[1] + p0.z * w1c[2]  + p0.w * w1c[3];
            a += p1.x * w1c[4] + p1.y * w1c[5] + p1.z * w1c[6]  + p1.w * w1c[7];
            a += p2.x * w1c[8] + p2.y * w1c[9] + p2.z * w1c[10] + p2.w * w1c[11];
            float h = __fdividef(a, 1.0f + __expf(-a));   // silu
            if (u == 0) acc0 += h; else if (u == 1) acc1 += h; else acc2 += h;
        }
    }
    g_hacc[(size_t)node_r * HH + t] = acc0 + acc1 + acc2;
}

// ---------------------------------------------------------------------------
// Kernel 3: per-node tail.  aug = (hacc/99)@W2 + b2 + cv@Wr[3:6] + br;
// p = relu(relu(aug@W3+b3)@W4+b4); pred = p@W5+b5; out = in + rotate(pred).
// 32 nodes per block, all weights staged in dynamic smem (~207 KB),
// 2 nodes processed per matvec pass for ILP + shared weight reads.
// ---------------------------------------------------------------------------
__global__ __launch_bounds__(128) void node_mlp_kernel(
    const float* __restrict__ inp,
    const float* __restrict__ W2, const float* __restrict__ b2,
    const float* __restrict__ Wr, const float* __restrict__ br,
    const float* __restrict__ W3, const float* __restrict__ b3,
    const float* __restrict__ W4, const float* __restrict__ b4,
    const float* __restrict__ W5, const float* __restrict__ b5,
    float* __restrict__ out)
{
    extern __shared__ float sm[];
    float* W2s = sm;                 // 16384
    float* W3s = W2s + 16384;        // 16384
    float* W4s = W3s + 16384;        // 16384
    float* W5s = W4s + 16384;        // 768
    float* Wrs = W5s + 768;          // 384 (rows 3..5)
    float* b2s = Wrs + 384;          // 128
    float* b3s = b2s + 128;          // 128
    float* b4s = b3s + 128;          // 128
    float* brs = b4s + 128;          // 128
    float* b5s = brs + 128;          // 8
    float* hs   = b5s + 8;           // 256
    float* augs = hs + 256;          // 256
    float* p1s  = augs + 256;        // 256
    float* p2s  = p1s + 256;         // 256
    float* preds = p2s + 256;        // 16

    int t = threadIdx.x;
    for (int i = t; i < 16384; i += 128) { W2s[i] = W2[i]; W3s[i] = W3[i]; W4s[i] = W4[i]; }
    for (int i = t; i < 768; i += 128) W5s[i] = W5[i];
    for (int i = t; i < 384; i += 128) Wrs[i] = Wr[384 + i];   // rows 3..5 of (6,128)
    b2s[t] = b2[t]; b3s[t] = b3[t]; b4s[t] = b4[t]; brs[t] = br[t];
    if (t < 6) b5s[t] = b5[t];
    __syncthreads();

    const float inv99 = 1.0f / 99.0f;
    for (int it = 0; it < 16; it++) {
        int n0 = blockIdx.x * 32 + it * 2;
        hs[t]       = g_hacc[(size_t)n0 * HH + t] * inv99;
        hs[128 + t] = g_hacc[(size_t)(n0 + 1) * HH + t] * inv99;
        __syncthreads();

        float a0 = b2s[t] + brs[t];
        float a1 = a0;
#pragma unroll 4
        for (int k = 0; k < 128; k++) {
            float w = W2s[k * 128 + t];
            a0 += hs[k] * w; a1 += hs[128 + k] * w;
        }
        {
            float c00 = g_cv[n0 * 3], c01 = g_cv[n0 * 3 + 1], c02 = g_cv[n0 * 3 + 2];
            float c10 = g_cv[(n0 + 1) * 3], c11 = g_cv[(n0 + 1) * 3 + 1], c12 = g_cv[(n0 + 1) * 3 + 2];
            float w0 = Wrs[t], w1 = Wrs[128 + t], w2 = Wrs[256 + t];
            a0 += c00 * w0 + c01 * w1 + c02 * w2;
            a1 += c10 * w0 + c11 * w1 + c12 * w2;
        }
        augs[t] = a0; augs[128 + t] = a1;
        __syncthreads();

        a0 = b3s[t]; a1 = b3s[t];
#pragma unroll 4
        for (int k = 0; k < 128; k++) {
            float w = W3s[k * 128 + t];
            a0 += augs[k] * w; a1 += augs[128 + k] * w;
        }
        p1s[t] = fmaxf(a0, 0.0f); p1s[128 + t] = fmaxf(a1, 0.0f);
        __syncthreads();

        a0 = b4s[t]; a1 = b4s[t];
#pragma unroll 4
        for (int k = 0; k < 128; k++) {
            float w = W4s[k * 128 + t];
            a0 += p1s[k] * w; a1 += p1s[128 + k] * w;
        }
        p2s[t] = fmaxf(a0, 0.0f); p2s[128 + t] = fmaxf(a1, 0.0f);
        __syncthreads();

        if (t < 12) {
            int un = t / 6, j = t % 6;
            float s = b5s[j];
#pragma unroll 4
            for (int k = 0; k < 128; k++) s += p2s[un * 128 + k] * W5s[k * 6 + j];
            preds[un * 8 + j] = s;
        }
        __syncthreads();
        if (t < 12) {
            int un = t / 6, j = t % 6;
            int node = n0 + un;
            const float* R = g_R + (size_t)node * 9;
            int i = j % 3, off = (j / 3) * 3;
            float gl = R[i * 3 + 0] * preds[un * 8 + off + 0]
                     + R[i * 3 + 1] * preds[un * 8 + off + 1]
                     + R[i * 3 + 2] * preds[un * 8 + off + 2];
            out[(size_t)node * 6 + j] = inp[(size_t)node * 6 + j] + gl;
        }
        __syncthreads();
    }
}

// ---------------------------------------------------------------------------
extern "C" void kernel_launch(void* const* d_in, const int* in_sizes, int n_in,
                              void* d_out, int out_size)
{
    const float* inp = (const float*)d_in[0];
    const float* W1  = (const float*)d_in[1];
    const float* b1  = (const float*)d_in[2];
    const float* W2  = (const float*)d_in[3];
    const float* b2  = (const float*)d_in[4];
    const float* Wr  = (const float*)d_in[5];
    const float* br  = (const float*)d_in[6];
    const float* W3  = (const float*)d_in[7];
    const float* b3  = (const float*)d_in[8];
    const float* W4  = (const float*)d_in[9];
    const float* b4  = (const float*)d_in[10];
    const float* W5  = (const float*)d_in[11];
    const float* b5  = (const float*)d_in[12];
    float* out = (float*)d_out;

    const int SMEM3 = 51864 * 4;  // ~207 KB dynamic smem for node_mlp
    cudaFuncSetAttribute(node_mlp_kernel,
                         cudaFuncAttributeMaxDynamicSharedMemorySize, SMEM3);

    node_pre_kernel<<<NODES / 128, 128>>>(inp);
    edge_agg_kernel<<<NODES, 128>>>(inp, W1, b1);
    node_mlp_kernel<<<NODES / 32, 128, SMEM3>>>(inp, W2, b2, Wr, br,
                                                W3, b3, W4, b4, W5, b5, out);
}

// round 2
// speedup vs baseline: 1.5324x; 1.5324x over previous
#include <cuda_runtime.h>
#include <math.h>

#define BB 128
#define NN 100
#define HH 128
#define NODES (BB*NN)          // 12800
#define PI_F 3.14159265358979323846f
#define EPS_F 1e-7f

// Scratch (allocation-free rule: device globals)
__device__ float g_R[NODES * 9];
__device__ float g_cv[NODES * 3];
__device__ float g_hacc[NODES * HH];

typedef unsigned long long u64;

// ---- packed f32x2 helpers (FFMA2 path: only reachable via PTX) ------------
__device__ __forceinline__ u64 fma2(u64 a, u64 b, u64 c) {
    u64 d;
    asm("fma.rn.f32x2 %0, %1, %2, %3;" : "=l"(d) : "l"(a), "l"(b), "l"(c));
    return d;
}
__device__ __forceinline__ u64 pack2(float lo, float hi) {
    u64 d; asm("mov.b64 %0, {%1, %2};" : "=l"(d) : "f"(lo), "f"(hi)); return d;
}
__device__ __forceinline__ void unpack2(u64 v, float& lo, float& hi) {
    asm("mov.b64 {%0, %1}, %2;" : "=f"(lo), "=f"(hi) : "l"(v));
}
__device__ __forceinline__ float tanh_fast(float x) {
    float r; asm("tanh.approx.f32 %0, %1;" : "=f"(r) : "f"(x)); return r;
}

__device__ __forceinline__ void vel_to_R(float vx, float vy, float vz, float* R) {
    float rho = sqrtf(vx * vx + vy * vy + vz * vz);
    float theta = atan2f(vy, vx);
    if (theta < 0.0f) theta += 2.0f * PI_F;   // mirror reference numerics
    float c = vz / (rho + EPS_F);
    c = fminf(fmaxf(c, -1.0f), 1.0f);
    float phi = acosf(c);
    float st, ct, sp, cp;
    sincosf(theta, &st, &ct);
    sincosf(phi, &sp, &cp);
    R[0] = cp * ct; R[1] = -st;  R[2] = sp * ct;
    R[3] = cp * st; R[4] = ct;   R[5] = sp * st;
    R[6] = -sp;     R[7] = 0.0f; R[8] = cp;
}

// ---------------------------------------------------------------------------
// Kernel 1: per-node rotation matrix + canonical velocity
// ---------------------------------------------------------------------------
__global__ void node_pre_kernel(const float* __restrict__ inp) {
    int idx = blockIdx.x * 128 + threadIdx.x;
    if (idx >= NODES) return;
    const float* v = inp + (size_t)idx * 6 + 3;
    float vx = v[0], vy = v[1], vz = v[2];
    float R[9];
    vel_to_R(vx, vy, vz, R);
#pragma unroll
    for (int i = 0; i < 9; i++) g_R[idx * 9 + i] = R[i];
    g_cv[idx * 3 + 0] = R[0] * vx + R[3] * vy + R[6] * vz;
    g_cv[idx * 3 + 1] = R[1] * vx + R[4] * vy + R[7] * vz;
    g_cv[idx * 3 + 2] = R[2] * vx + R[5] * vy + R[8] * vz;
}

// ---------------------------------------------------------------------------
// Kernel 2: per (b, recv) block. Threads 0..98 build the 12 varying edge
// features into a PAIRED smem layout (float2 per feature = two edges), then
// all 128 threads accumulate  hacc[t] = sum_e silu(ea_e @ W1)_t  using
// FFMA2 (two edges per instruction) + MUFU.TANH silu. W2 deferred (linearity).
// ---------------------------------------------------------------------------
__global__ __launch_bounds__(128) void edge_agg_kernel(
    const float* __restrict__ inp,
    const float* __restrict__ W1,
    const float* __restrict__ b1)
{
    // ea2[p][k] = (feature k of edge 2p, feature k of edge 2p+1)
    __shared__ __align__(16) float2 ea2[50][12];
    int b = blockIdx.x / NN;
    int r = blockIdx.x % NN;
    int t = threadIdx.x;
    int node_r = b * NN + r;

    // W1 column (varying rows 0..11) for this thread's hidden channel
    float w1c[12];
#pragma unroll
    for (int k = 0; k < 12; k++) w1c[k] = W1[k * HH + t];
    u64 wk2[12];
#pragma unroll
    for (int k = 0; k < 12; k++) wk2[k] = pack2(w1c[k], w1c[k]);

    float cv0 = g_cv[node_r * 3 + 0];
    float cv1 = g_cv[node_r * 3 + 1];
    float cv2 = g_cv[node_r * 3 + 2];
    // rows 12..14 multiply exact zeros; rows 15..17 multiply canon_vel(recv)
    float base = b1[t] + cv0 * W1[15 * HH + t] + cv1 * W1[16 * HH + t]
                       + cv2 * W1[17 * HH + t];
    u64 base2 = pack2(base, base);

    if (t < NN - 1) {
        int s = t + (t >= r ? 1 : 0);
        int node_s = b * NN + s;
        const float* xj = inp + (size_t)node_s * 6;
        const float* xi = inp + (size_t)node_r * 6;
        float Rr[9], Rs[9];
#pragma unroll
        for (int i = 0; i < 9; i++) { Rr[i] = g_R[node_r * 9 + i]; Rs[i] = g_R[node_s * 9 + i]; }

        float rel0 = xj[0] - xi[0], rel1 = xj[1] - xi[1], rel2 = xj[2] - xi[2];
        float rr0 = Rr[0] * rel0 + Rr[3] * rel1 + Rr[6] * rel2;
        float rr1 = Rr[1] * rel0 + Rr[4] * rel1 + Rr[7] * rel2;
        float rr2 = Rr[2] * rel0 + Rr[5] * rel1 + Rr[8] * rel2;
        float ro00 = Rr[0] * Rs[0] + Rr[3] * Rs[3] + Rr[6] * Rs[6];
        float ro10 = Rr[1] * Rs[0] + Rr[4] * Rs[3] + Rr[7] * Rs[6];
        float ro20 = Rr[2] * Rs[0] + Rr[5] * Rs[3] + Rr[8] * Rs[6];
        float ro21 = Rr[2] * Rs[1] + Rr[5] * Rs[4] + Rr[8] * Rs[7];
        float ro22 = Rr[2] * Rs[2] + Rr[5] * Rs[5] + Rr[8] * Rs[8];

        float f[12];
        f[0] = rr0; f[1] = rr1; f[2] = rr2;
        f[3] = atan2f(ro10, ro00) * (1.0f / PI_F);
        float sa = fminf(fmaxf(-ro20, -1.0f), 1.0f);
        f[4] = asinf(sa) * (1.0f / PI_F);
        f[5] = atan2f(ro21, ro22) * (1.0f / PI_F);
        f[6] = sqrtf(rel0 * rel0 + rel1 * rel1 + rel2 * rel2);
        f[7] = atan2f(rr1, rr0);
        float rho_e = sqrtf(rr0 * rr0 + rr1 * rr1 + rr2 * rr2);
        float cc = rr2 / (rho_e + EPS_F);
        cc = fminf(fmaxf(cc, -1.0f), 1.0f);
        f[8] = acosf(cc);
        float vj0 = xj[3], vj1 = xj[4], vj2 = xj[5];
        f[9]  = Rr[0] * vj0 + Rr[3] * vj1 + Rr[6] * vj2;
        f[10] = Rr[1] * vj0 + Rr[4] * vj1 + Rr[7] * vj2;
        f[11] = Rr[2] * vj0 + Rr[5] * vj1 + Rr[8] * vj2;

        float* dst = (float*)&ea2[t >> 1][0];
        int u = t & 1;
#pragma unroll
        for (int k = 0; k < 12; k++) dst[2 * k + u] = f[k];
    }
    __syncthreads();

    float acc0 = 0.0f, acc1 = 0.0f;
#pragma unroll 7
    for (int p = 0; p < 49; p++) {
        const ulonglong2* q = (const ulonglong2*)&ea2[p][0];
        ulonglong2 c0 = q[0], c1 = q[1], c2 = q[2], c3 = q[3], c4 = q[4], c5 = q[5];
        u64 a2 = base2;
        a2 = fma2(c0.x, wk2[0], a2);  a2 = fma2(c0.y, wk2[1], a2);
        a2 = fma2(c1.x, wk2[2], a2);  a2 = fma2(c1.y, wk2[3], a2);
        a2 = fma2(c2.x, wk2[4], a2);  a2 = fma2(c2.y, wk2[5], a2);
        a2 = fma2(c3.x, wk2[6], a2);  a2 = fma2(c3.y, wk2[7], a2);
        a2 = fma2(c4.x, wk2[8], a2);  a2 = fma2(c4.y, wk2[9], a2);
        a2 = fma2(c5.x, wk2[10], a2); a2 = fma2(c5.y, wk2[11], a2);
        float a, bq;
        unpack2(a2, a, bq);
        float m0 = 0.5f * a, m1 = 0.5f * bq;
        acc0 = fmaf(m0, tanh_fast(m0), acc0 + m0);   // silu = m + m*tanh(m)
        acc1 = fmaf(m1, tanh_fast(m1), acc1 + m1);
    }
    // leftover edge 98 (stored in the .x slots of pair 49)
    {
        const float* e = (const float*)&ea2[49][0];
        float a = base;
#pragma unroll
        for (int k = 0; k < 12; k++) a = fmaf(e[2 * k], w1c[k], a);
        float m = 0.5f * a;
        acc0 = fmaf(m, tanh_fast(m), acc0 + m);
    }
    g_hacc[(size_t)node_r * HH + t] = acc0 + acc1;
}

// ---------------------------------------------------------------------------
// Kernel 3: warp-per-node MLP tail. 256 threads (8 warps) per block, weights
// staged once in smem; each warp walks its nodes with NO block syncs.
// Lane owns 4 output channels; FFMA2 inner loops; W5 epilogue via register
// partials + shfl_xor reduction; lanes 0..5 write the rotated output.
// ---------------------------------------------------------------------------
#define MLP_BLOCKS 160
#define MLP_WARPS 8
#define NODES_PER_WARP (NODES / (MLP_BLOCKS * MLP_WARPS))   // 10

// smem float offsets
#define OFF_W2 0
#define OFF_W3 16384
#define OFF_W4 32768
#define OFF_W5 49152            // 768
#define OFF_WR 49920            // 384 (rows 3..5 of Wr)
#define OFF_B2R 50304           // 128 (b2 + br)
#define OFF_B3 50432
#define OFF_B4 50560
#define OFF_B5 50688            // 8 (padded)
#define OFF_XS 50696            // 8 warps * 256
#define SMEM_FLOATS (OFF_XS + MLP_WARPS * 256)

__global__ __launch_bounds__(256) void node_mlp_kernel(
    const float* __restrict__ inp,
    const float* __restrict__ W2, const float* __restrict__ b2,
    const float* __restrict__ Wr, const float* __restrict__ br,
    const float* __restrict__ W3, const float* __restrict__ b3,
    const float* __restrict__ W4, const float* __restrict__ b4,
    const float* __restrict__ W5, const float* __restrict__ b5,
    float* __restrict__ out)
{
    extern __shared__ float sm[];
    int t = threadIdx.x;
    for (int i = t; i < 16384; i += 256) {
        sm[OFF_W2 + i] = W2[i];
        sm[OFF_W3 + i] = W3[i];
        sm[OFF_W4 + i] = W4[i];
    }
    for (int i = t; i < 768; i += 256) sm[OFF_W5 + i] = W5[i];
    for (int i = t; i < 384; i += 256) sm[OFF_WR + i] = Wr[384 + i];  // rows 3..5
    if (t < 128) {
        sm[OFF_B2R + t] = b2[t] + br[t];
        sm[OFF_B3 + t] = b3[t];
        sm[OFF_B4 + t] = b4[t];
    }
    if (t < 6) sm[OFF_B5 + t] = b5[t];
    __syncthreads();

    int warp = t >> 5;
    int lane = t & 31;
    int c4 = lane * 4;
    float* xbuf = sm + OFF_XS + warp * 256;   // [0..127]=in, [128..255]=out
    const float inv99 = 1.0f / 99.0f;

    for (int ni = 0; ni < NODES_PER_WARP; ni++) {
        int node = (blockIdx.x * MLP_WARPS + warp) * NODES_PER_WARP + ni;

        // stage h/99 into xbuf[0..127]
        float4 hv = *(const float4*)&g_hacc[(size_t)node * HH + c4];
        *(float4*)&xbuf[c4] = make_float4(hv.x * inv99, hv.y * inv99,
                                          hv.z * inv99, hv.w * inv99);
        __syncwarp();

        // ---- layer A: aug = x@W2 + (b2+br) + cv@Wr  (no activation) ----
        {
            u64 ax = pack2(sm[OFF_B2R + c4],     sm[OFF_B2R + c4 + 1]);
            u64 ay = pack2(sm[OFF_B2R + c4 + 2], sm[OFF_B2R + c4 + 3]);
#pragma unroll 8
            for (int k4 = 0; k4 < 32; k4++) {
                float4 xv = *(const float4*)&xbuf[k4 * 4];
                {
                    const ulonglong2 wv = *(const ulonglong2*)&sm[OFF_W2 + (k4*4+0)*128 + c4];
                    u64 x2 = pack2(xv.x, xv.x);
                    ax = fma2(x2, wv.x, ax); ay = fma2(x2, wv.y, ay);
                }
                {
                    const ulonglong2 wv = *(const ulonglong2*)&sm[OFF_W2 + (k4*4+1)*128 + c4];
                    u64 x2 = pack2(xv.y, xv.y);
                    ax = fma2(x2, wv.x, ax); ay = fma2(x2, wv.y, ay);
                }
                {
                    const ulonglong2 wv = *(const ulonglong2*)&sm[OFF_W2 + (k4*4+2)*128 + c4];
                    u64 x2 = pack2(xv.z, xv.z);
                    ax = fma2(x2, wv.x, ax); ay = fma2(x2, wv.y, ay);
                }
                {
                    const ulonglong2 wv = *(const ulonglong2*)&sm[OFF_W2 + (k4*4+3)*128 + c4];
                    u64 x2 = pack2(xv.w, xv.w);
                    ax = fma2(x2, wv.x, ax); ay = fma2(x2, wv.y, ay);
                }
            }
            float a0, a1, a2, a3;
            unpack2(ax, a0, a1); unpack2(ay, a2, a3);
            float cvx = g_cv[node * 3], cvy = g_cv[node * 3 + 1], cvz = g_cv[node * 3 + 2];
            float4 w0 = *(const float4*)&sm[OFF_WR + c4];
            float4 w1 = *(const float4*)&sm[OFF_WR + 128 + c4];
            float4 w2v = *(const float4*)&sm[OFF_WR + 256 + c4];
            a0 += cvx * w0.x + cvy * w1.x + cvz * w2v.x;
            a1 += cvx * w0.y + cvy * w1.y + cvz * w2v.y;
            a2 += cvx * w0.z + cvy * w1.z + cvz * w2v.z;
            a3 += cvx * w0.w + cvy * w1.w + cvz * w2v.w;
            *(float4*)&xbuf[128 + c4] = make_float4(a0, a1, a2, a3);
        }
        __syncwarp();

        // ---- layer B: p1 = relu(aug@W3 + b3) ----
        {
            u64 ax = pack2(sm[OFF_B3 + c4],     sm[OFF_B3 + c4 + 1]);
            u64 ay = pack2(sm[OFF_B3 + c4 + 2], sm[OFF_B3 + c4 + 3]);
#pragma unroll 8
            for (int k4 = 0; k4 < 32; k4++) {
                float4 xv = *(const float4*)&xbuf[128 + k4 * 4];
                {
                    const ulonglong2 wv = *(const ulonglong2*)&sm[OFF_W3 + (k4*4+0)*128 + c4];
                    u64 x2 = pack2(xv.x, xv.x);
                    ax = fma2(x2, wv.x, ax); ay = fma2(x2, wv.y, ay);
                }
                {
                    const ulonglong2 wv = *(const ulonglong2*)&sm[OFF_W3 + (k4*4+1)*128 + c4];
                    u64 x2 = pack2(xv.y, xv.y);
                    ax = fma2(x2, wv.x, ax); ay = fma2(x2, wv.y, ay);
                }
                {
                    const ulonglong2 wv = *(const ulonglong2*)&sm[OFF_W3 + (k4*4+2)*128 + c4];
                    u64 x2 = pack2(xv.z, xv.z);
                    ax = fma2(x2, wv.x, ax); ay = fma2(x2, wv.y, ay);
                }
                {
                    const ulonglong2 wv = *(const ulonglong2*)&sm[OFF_W3 + (k4*4+3)*128 + c4];
                    u64 x2 = pack2(xv.w, xv.w);
                    ax = fma2(x2, wv.x, ax); ay = fma2(x2, wv.y, ay);
                }
            }
            float a0, a1, a2, a3;
            unpack2(ax, a0, a1); unpack2(ay, a2, a3);
            *(float4*)&xbuf[c4] = make_float4(fmaxf(a0, 0.f), fmaxf(a1, 0.f),
                                              fmaxf(a2, 0.f), fmaxf(a3, 0.f));
        }
        __syncwarp();

        // ---- layer C: p2 = relu(p1@W4 + b4)  (kept in registers) ----
        float p20, p21, p22, p23;
        {
            u64 ax = pack2(sm[OFF_B4 + c4],     sm[OFF_B4 + c4 + 1]);
            u64 ay = pack2(sm[OFF_B4 + c4 + 2], sm[OFF_B4 + c4 + 3]);
#pragma unroll 8
            for (int k4 = 0; k4 < 32; k4++) {
                float4 xv = *(const float4*)&xbuf[k4 * 4];
                {
                    const ulonglong2 wv = *(const ulonglong2*)&sm[OFF_W4 + (k4*4+0)*128 + c4];
                    u64 x2 = pack2(xv.x, xv.x);
                    ax = fma2(x2, wv.x, ax); ay = fma2(x2, wv.y, ay);
                }
                {
                    const ulonglong2 wv = *(const ulonglong2*)&sm[OFF_W4 + (k4*4+1)*128 + c4];
                    u64 x2 = pack2(xv.y, xv.y);
                    ax = fma2(x2, wv.x, ax); ay = fma2(x2, wv.y, ay);
                }
                {
                    const ulonglong2 wv = *(const ulonglong2*)&sm[OFF_W4 + (k4*4+2)*128 + c4];
                    u64 x2 = pack2(xv.z, xv.z);
                    ax = fma2(x2, wv.x, ax); ay = fma2(x2, wv.y, ay);
                }
                {
                    const ulonglong2 wv = *(const ulonglong2*)&sm[OFF_W4 + (k4*4+3)*128 + c4];
                    u64 x2 = pack2(xv.w, xv.w);
                    ax = fma2(x2, wv.x, ax); ay = fma2(x2, wv.y, ay);
                }
            }
            float a0, a1, a2, a3;
            unpack2(ax, a0, a1); unpack2(ay, a2, a3);
            p20 = fmaxf(a0, 0.f); p21 = fmaxf(a1, 0.f);
            p22 = fmaxf(a2, 0.f); p23 = fmaxf(a3, 0.f);
        }

        // ---- W5 epilogue: per-lane partials over own 4 rows, warp-reduce ----
        float sj[6];
#pragma unroll
        for (int j = 0; j < 6; j++) {
            sj[j] = p20 * sm[OFF_W5 + (c4 + 0) * 6 + j]
                  + p21 * sm[OFF_W5 + (c4 + 1) * 6 + j]
                  + p22 * sm[OFF_W5 + (c4 + 2) * 6 + j]
                  + p23 * sm[OFF_W5 + (c4 + 3) * 6 + j];
        }
#pragma unroll
        for (int j = 0; j < 6; j++) {
#pragma unroll
            for (int off = 16; off > 0; off >>= 1)
                sj[j] += __shfl_xor_sync(0xffffffffu, sj[j], off);
        }
        if (lane < 6) {
            int j = lane;
            float pred0 = sj[0] + sm[OFF_B5 + 0];
            float pred1 = sj[1] + sm[OFF_B5 + 1];
            float pred2 = sj[2] + sm[OFF_B5 + 2];
            float pred3 = sj[3] + sm[OFF_B5 + 3];
            float pred4 = sj[4] + sm[OFF_B5 + 4];
            float pred5 = sj[5] + sm[OFF_B5 + 5];
            int i = j % 3, offp = (j / 3) * 3;
            const float* R = g_R + (size_t)node * 9;
            float q0 = (offp == 0) ? pred0 : pred3;
            float q1 = (offp == 0) ? pred1 : pred4;
            float q2 = (offp == 0) ? pred2 : pred5;
            float gl = R[i * 3 + 0] * q0 + R[i * 3 + 1] * q1 + R[i * 3 + 2] * q2;
            out[(size_t)node * 6 + j] = inp[(size_t)node * 6 + j] + gl;
        }
        __syncwarp();
    }
}

// ---------------------------------------------------------------------------
extern "C" void kernel_launch(void* const* d_in, const int* in_sizes, int n_in,
                              void* d_out, int out_size)
{
    const float* inp = (const float*)d_in[0];
    const float* W1  = (const float*)d_in[1];
    const float* b1  = (const float*)d_in[2];
    const float* W2  = (const float*)d_in[3];
    const float* b2  = (const float*)d_in[4];
    const float* Wr  = (const float*)d_in[5];
    const float* br  = (const float*)d_in[6];
    const float* W3  = (const float*)d_in[7];
    const float* b3  = (const float*)d_in[8];
    const float* W4  = (const float*)d_in[9];
    const float* b4  = (const float*)d_in[10];
    const float* W5  = (const float*)d_in[11];
    const float* b5  = (const float*)d_in[12];
    float* out = (float*)d_out;

    const int SMEM3 = SMEM_FLOATS * 4;   // ~211 KB dynamic smem
    cudaFuncSetAttribute(node_mlp_kernel,
                         cudaFuncAttributeMaxDynamicSharedMemorySize, SMEM3);

    node_pre_kernel<<<NODES / 128, 128>>>(inp);
    edge_agg_kernel<<<NODES, 128>>>(inp, W1, b1);
    node_mlp_kernel<<<MLP_BLOCKS, 256, SMEM3>>>(inp, W2, b2, Wr, br,
                                                W3, b3, W4, b4, W5, b5, out);
}

// round 6
// speedup vs baseline: 2.8555x; 1.8634x over previous
#include <cuda_runtime.h>
#include <math.h>

#define BB 128
#define NN 100
#define HH 128
#define NODES (BB*NN)          // 12800
#define NODES_PAD 12864        // 134 blocks * 96 nodes
#define PI_F 3.14159265358979323846f
#define EPS_F 1e-7f

// Scratch (allocation-free rule: device globals; BSS zero-init covers padding)
__device__ float g_R[NODES_PAD * 9];
__device__ float g_cv[NODES_PAD * 3];
__device__ float g_hacc[NODES_PAD * HH];

typedef unsigned long long u64;

// ---- packed f32x2 helpers -------------------------------------------------
__device__ __forceinline__ u64 fma2(u64 a, u64 b, u64 c) {
    u64 d;
    asm("fma.rn.f32x2 %0, %1, %2, %3;" : "=l"(d) : "l"(a), "l"(b), "l"(c));
    return d;
}
__device__ __forceinline__ u64 mul2(u64 a, u64 b) {
    u64 d; asm("mul.rn.f32x2 %0, %1, %2;" : "=l"(d) : "l"(a), "l"(b)); return d;
}
__device__ __forceinline__ u64 add2(u64 a, u64 b) {
    u64 d; asm("add.rn.f32x2 %0, %1, %2;" : "=l"(d) : "l"(a), "l"(b)); return d;
}
__device__ __forceinline__ u64 pack2(float lo, float hi) {
    u64 d; asm("mov.b64 %0, {%1, %2};" : "=l"(d) : "f"(lo), "f"(hi)); return d;
}
__device__ __forceinline__ void unpack2(u64 v, float& lo, float& hi) {
    asm("mov.b64 {%0, %1}, %2;" : "=f"(lo), "=f"(hi) : "l"(v));
}
__device__ __forceinline__ float tanh_fast(float x) {
    float r; asm("tanh.approx.f32 %0, %1;" : "=f"(r) : "f"(x)); return r;
}

__device__ __forceinline__ void vel_to_R(float vx, float vy, float vz, float* R) {
    float rho = sqrtf(vx * vx + vy * vy + vz * vz);
    float theta = atan2f(vy, vx);
    if (theta < 0.0f) theta += 2.0f * PI_F;
    float c = vz / (rho + EPS_F);
    c = fminf(fmaxf(c, -1.0f), 1.0f);
    float phi = acosf(c);
    float st, ct, sp, cp;
    sincosf(theta, &st, &ct);
    sincosf(phi, &sp, &cp);
    R[0] = cp * ct; R[1] = -st;  R[2] = sp * ct;
    R[3] = cp * st; R[4] = ct;   R[5] = sp * st;
    R[6] = -sp;     R[7] = 0.0f; R[8] = cp;
}

// ---------------------------------------------------------------------------
// Kernel 1: per-node rotation matrix + canonical velocity
// ---------------------------------------------------------------------------
__global__ void node_pre_kernel(const float* __restrict__ inp) {
    int idx = blockIdx.x * 128 + threadIdx.x;
    if (idx >= NODES) return;
    const float* v = inp + (size_t)idx * 6 + 3;
    float vx = v[0], vy = v[1], vz = v[2];
    float R[9];
    vel_to_R(vx, vy, vz, R);
#pragma unroll
    for (int i = 0; i < 9; i++) g_R[idx * 9 + i] = R[i];
    g_cv[idx * 3 + 0] = R[0] * vx + R[3] * vy + R[6] * vz;
    g_cv[idx * 3 + 1] = R[1] * vx + R[4] * vy + R[7] * vz;
    g_cv[idx * 3 + 2] = R[2] * vx + R[5] * vy + R[8] * vz;
}

// ---------------------------------------------------------------------------
// Kernel 2: per (b, recv) block of 64 threads; each thread owns TWO hidden
// channels (t, t+64). Edge features paired in smem; pair 49 .y slot is zeroed
// and its spurious silu(base) contribution subtracted analytically.
// hacc[c] = sum_e silu(ea_e @ W1)_c   (W2 deferred by linearity)
// ---------------------------------------------------------------------------
__global__ __launch_bounds__(64) void edge_agg_kernel(
    const float* __restrict__ inp,
    const float* __restrict__ W1,
    const float* __restrict__ b1)
{
    __shared__ __align__(16) float2 ea2[50][12];
    int b = blockIdx.x / NN;
    int r = blockIdx.x % NN;
    int t = threadIdx.x;          // 0..63
    int node_r = b * NN + r;

    // packed weights for channels t and t+64 (varying rows 0..11)
    u64 wa[12], wb[12];
#pragma unroll
    for (int k = 0; k < 12; k++) {
        float x = W1[k * HH + t];
        float y = W1[k * HH + t + 64];
        wa[k] = pack2(x, x);
        wb[k] = pack2(y, y);
    }

    float cv0 = g_cv[node_r * 3 + 0];
    float cv1 = g_cv[node_r * 3 + 1];
    float cv2 = g_cv[node_r * 3 + 2];
    float baseA = b1[t]      + cv0 * W1[15 * HH + t]      + cv1 * W1[16 * HH + t]      + cv2 * W1[17 * HH + t];
    float baseB = b1[t + 64] + cv0 * W1[15 * HH + t + 64] + cv1 * W1[16 * HH + t + 64] + cv2 * W1[17 * HH + t + 64];
    u64 base2A = pack2(baseA, baseA);
    u64 base2B = pack2(baseB, baseB);

    // build edge features: thread t handles edges t and t+64 (if <99)
    {
        float Rr[9];
#pragma unroll
        for (int i = 0; i < 9; i++) Rr[i] = g_R[node_r * 9 + i];
        const float* xi = inp + (size_t)node_r * 6;
        float xi0 = xi[0], xi1 = xi[1], xi2 = xi[2];

        for (int e = t; e < NN - 1; e += 64) {
            int s = e + (e >= r ? 1 : 0);
            int node_s = b * NN + s;
            const float* xj = inp + (size_t)node_s * 6;
            float Rs[9];
#pragma unroll
            for (int i = 0; i < 9; i++) Rs[i] = g_R[node_s * 9 + i];

            float rel0 = xj[0] - xi0, rel1 = xj[1] - xi1, rel2 = xj[2] - xi2;
            float rr0 = Rr[0] * rel0 + Rr[3] * rel1 + Rr[6] * rel2;
            float rr1 = Rr[1] * rel0 + Rr[4] * rel1 + Rr[7] * rel2;
            float rr2 = Rr[2] * rel0 + Rr[5] * rel1 + Rr[8] * rel2;
            float ro00 = Rr[0] * Rs[0] + Rr[3] * Rs[3] + Rr[6] * Rs[6];
            float ro10 = Rr[1] * Rs[0] + Rr[4] * Rs[3] + Rr[7] * Rs[6];
            float ro20 = Rr[2] * Rs[0] + Rr[5] * Rs[3] + Rr[8] * Rs[6];
            float ro21 = Rr[2] * Rs[1] + Rr[5] * Rs[4] + Rr[8] * Rs[7];
            float ro22 = Rr[2] * Rs[2] + Rr[5] * Rs[5] + Rr[8] * Rs[8];

            float f[12];
            f[0] = rr0; f[1] = rr1; f[2] = rr2;
            f[3] = atan2f(ro10, ro00) * (1.0f / PI_F);
            float sa = fminf(fmaxf(-ro20, -1.0f), 1.0f);
            f[4] = asinf(sa) * (1.0f / PI_F);
            f[5] = atan2f(ro21, ro22) * (1.0f / PI_F);
            f[6] = sqrtf(rel0 * rel0 + rel1 * rel1 + rel2 * rel2);
            f[7] = atan2f(rr1, rr0);
            float rho_e = sqrtf(rr0 * rr0 + rr1 * rr1 + rr2 * rr2);
            float cc = rr2 / (rho_e + EPS_F);
            cc = fminf(fmaxf(cc, -1.0f), 1.0f);
            f[8] = acosf(cc);
            float vj0 = xj[3], vj1 = xj[4], vj2 = xj[5];
            f[9]  = Rr[0] * vj0 + Rr[3] * vj1 + Rr[6] * vj2;
            f[10] = Rr[1] * vj0 + Rr[4] * vj1 + Rr[7] * vj2;
            f[11] = Rr[2] * vj0 + Rr[5] * vj1 + Rr[8] * vj2;

            float* dst = (float*)&ea2[e >> 1][0];
            int u = e & 1;
#pragma unroll
            for (int k = 0; k < 12; k++) dst[2 * k + u] = f[k];
        }
    }
    // zero pair 49's .y lane (edge count 99 is odd)
    if (t == 63) {
        float* dst = (float*)&ea2[49][0];
#pragma unroll
        for (int k = 0; k < 12; k++) dst[2 * k + 1] = 0.0f;
    }
    __syncthreads();

    const u64 HALF2 = pack2(0.5f, 0.5f);
    u64 accMA = 0ull, accTA = 0ull, accMB = 0ull, accTB = 0ull;
#pragma unroll 5
    for (int p = 0; p < 50; p++) {
        const ulonglong2* q = (const ulonglong2*)&ea2[p][0];
        ulonglong2 c0 = q[0], c1 = q[1], c2 = q[2];
        u64 aA = base2A, aB = base2B;
        aA = fma2(c0.x, wa[0], aA);  aB = fma2(c0.x, wb[0], aB);
        aA = fma2(c0.y, wa[1], aA);  aB = fma2(c0.y, wb[1], aB);
        aA = fma2(c1.x, wa[2], aA);  aB = fma2(c1.x, wb[2], aB);
        aA = fma2(c1.y, wa[3], aA);  aB = fma2(c1.y, wb[3], aB);
        aA = fma2(c2.x, wa[4], aA);  aB = fma2(c2.x, wb[4], aB);
        aA = fma2(c2.y, wa[5], aA);  aB = fma2(c2.y, wb[5], aB);
        ulonglong2 c3 = q[3], c4 = q[4], c5 = q[5];
        aA = fma2(c3.x, wa[6], aA);  aB = fma2(c3.x, wb[6], aB);
        aA = fma2(c3.y, wa[7], aA);  aB = fma2(c3.y, wb[7], aB);
        aA = fma2(c4.x, wa[8], aA);  aB = fma2(c4.x, wb[8], aB);
        aA = fma2(c4.y, wa[9], aA);  aB = fma2(c4.y, wb[9], aB);
        aA = fma2(c5.x, wa[10], aA); aB = fma2(c5.x, wb[10], aB);
        aA = fma2(c5.y, wa[11], aA); aB = fma2(c5.y, wb[11], aB);

        // silu(a) = m + m*tanh(m), m = a/2; accumulate Sum(m) and Sum(m*t)
        u64 mA = mul2(aA, HALF2);
        u64 mB = mul2(aB, HALF2);
        float ml, mh;
        unpack2(mA, ml, mh);
        u64 tA = pack2(tanh_fast(ml), tanh_fast(mh));
        unpack2(mB, ml, mh);
        u64 tB = pack2(tanh_fast(ml), tanh_fast(mh));
        accMA = add2(accMA, mA);  accTA = fma2(mA, tA, accTA);
        accMB = add2(accMB, mB);  accTB = fma2(mB, tB, accTB);
    }

    // remove the padded lane's silu(base) and store
    {
        float m0, m1, s0, s1;
        unpack2(accMA, m0, m1); unpack2(accTA, s0, s1);
        float mb = 0.5f * baseA;
        float corr = fmaf(mb, tanh_fast(mb), mb);
        g_hacc[(size_t)node_r * HH + t] = (m0 + m1 + s0 + s1) - corr;

        unpack2(accMB, m0, m1); unpack2(accTB, s0, s1);
        mb = 0.5f * baseB;
        corr = fmaf(mb, tanh_fast(mb), mb);
        g_hacc[(size_t)node_r * HH + t + 64] = (m0 + m1 + s0 + s1) - corr;
    }
}

// ---------------------------------------------------------------------------
// Kernel 3: register-tiled GEMM MLP. 134 blocks x 384 threads; block owns 96
// nodes through all layers. Per layer: stage W transposed+swizzled in smem,
// GEMM 96x128 with warp-tile 32x32, thread micro-tile 8 nodes x 4 channels,
// k-pair-packed FFMA2. XOR swizzle keeps LDS.64 conflict-free.
// ---------------------------------------------------------------------------
#define MLP_BLOCKS 134
#define MLP_THREADS 384
#define NT 96

// smem float offsets
#define OFF_WT  0         // 16384  (Wt64: 128 ch x 64 u64)
#define OFF_A   16384     // 12288  (A64: 96 nodes x 64 u64)
#define OFF_B   28672     // 12288
#define OFF_W5T 40960     // 768  (W5t[j][k], stride 128)
#define OFF_WR  41728     // 384  (Wr rows 3..5)
#define OFF_B2R 42112     // 128  (b2+br)
#define OFF_B3  42240
#define OFF_B4  42368
#define OFF_B5  42496     // 8
#define SMEM_FL 42504

// A-buffer float index for (local node n, feature k)
__device__ __forceinline__ int a_fidx(int n, int k) {
    return (n * 64 + ((k >> 1) ^ ((n >> 3) & 3))) * 2 + (k & 1);
}

template <int MODE>   // 0: layer A (bias b2+br + cv@Wr, no act), 1: relu+bias
__device__ __forceinline__ void gemm_layer(
    const u64* __restrict__ Ain, float* __restrict__ Bout,
    const u64* __restrict__ Wt, const float* __restrict__ bias,
    int n0, const float* __restrict__ wrS)
{
    int t = threadIdx.x;
    int warp = t >> 5, lane = t & 31;
    int wr = warp >> 2, wc = warp & 3;       // 3 x 4 warp tiles
    int ng = lane >> 3, cg = lane & 7;
    int nb = wr * 32 + ng * 8;               // node base (8 nodes)
    int cb = wc * 32 + cg * 4;               // channel base (4 channels)
    int swzx = (nb >> 3) & 3;
    int swzw = cg;                           // (cb>>2)&7

    const u64* Ap = Ain + nb * 64;
    const u64* Wp = Wt + cb * 64;

    u64 acc[8][4];
#pragma unroll
    for (int i = 0; i < 8; i++)
#pragma unroll
        for (int j = 0; j < 4; j++) acc[i][j] = 0ull;

#pragma unroll 4
    for (int kp = 0; kp < 64; kp++) {
        int ox = kp ^ swzx;
        int ow = kp ^ swzw;
        u64 xr[8], wv[4];
#pragma unroll
        for (int i = 0; i < 8; i++) xr[i] = Ap[i * 64 + ox];
#pragma unroll
        for (int j = 0; j < 4; j++) wv[j] = Wp[j * 64 + ow];
#pragma unroll
        for (int i = 0; i < 8; i++)
#pragma unroll
            for (int j = 0; j < 4; j++) acc[i][j] = fma2(xr[i], wv[j], acc[i][j]);
    }

#pragma unroll
    for (int i = 0; i < 8; i++) {
        int n = nb + i;
        int sw = (n >> 3) & 3;
        float cvx = 0.f, cvy = 0.f, cvz = 0.f;
        if (MODE == 0) {
            int gn = n0 + n;
            cvx = g_cv[gn * 3 + 0]; cvy = g_cv[gn * 3 + 1]; cvz = g_cv[gn * 3 + 2];
        }
#pragma unroll
        for (int j = 0; j < 4; j++) {
            int c = cb + j;
            float lo, hi;
            unpack2(acc[i][j], lo, hi);
            float s = lo + hi + bias[c];
            if (MODE == 0) {
                s += cvx * wrS[c] + cvy * wrS[128 + c] + cvz * wrS[256 + c];
            } else {
                s = fmaxf(s, 0.0f);
            }
            Bout[(n * 64 + ((c >> 1) ^ sw)) * 2 + (c & 1)] = s;
        }
    }
}

__global__ __launch_bounds__(MLP_THREADS, 1) void node_mlp_kernel(
    const float* __restrict__ inp,
    const float* __restrict__ W2, const float* __restrict__ b2,
    const float* __restrict__ Wr, const float* __restrict__ br,
    const float* __restrict__ W3, const float* __restrict__ b3,
    const float* __restrict__ W4, const float* __restrict__ b4,
    const float* __restrict__ W5, const float* __restrict__ b5,
    float* __restrict__ out)
{
    extern __shared__ float sm[];
    int t = threadIdx.x;
    int n0 = blockIdx.x * NT;
    const float inv99 = 1.0f / 99.0f;

    // one-time stages: A0 (h/99), small weights, biases
    for (int idx = t; idx < NT * 128; idx += MLP_THREADS) {
        int n = idx >> 7, k = idx & 127;
        sm[OFF_A + a_fidx(n, k)] = g_hacc[(size_t)(n0 + n) * 128 + k] * inv99;
    }
    for (int idx = t; idx < 768; idx += MLP_THREADS) {
        int k = idx / 6, j = idx % 6;
        sm[OFF_W5T + j * 128 + k] = W5[idx];
    }
    for (int idx = t; idx < 384; idx += MLP_THREADS) sm[OFF_WR + idx] = Wr[384 + idx];
    if (t < 128) {
        sm[OFF_B2R + t] = b2[t] + br[t];
        sm[OFF_B3 + t] = b3[t];
        sm[OFF_B4 + t] = b4[t];
    }
    if (t < 6) sm[OFF_B5 + t] = b5[t];

    u64* A64 = (u64*)(sm + OFF_A);
    u64* B64 = (u64*)(sm + OFF_B);
    u64* Wt64 = (u64*)(sm + OFF_WT);

    // ---- layer A: Wt <- W2^T ----
    for (int idx = t; idx < 16384; idx += MLP_THREADS) {
        int k = idx >> 7, c = idx & 127;
        sm[OFF_WT + (c * 64 + ((k >> 1) ^ ((c >> 2) & 7))) * 2 + (k & 1)] = W2[idx];
    }
    __syncthreads();
    gemm_layer<0>(A64, sm + OFF_B, Wt64, sm + OFF_B2R, n0, sm + OFF_WR);
    __syncthreads();

    // ---- layer B: Wt <- W3^T ----
    for (int idx = t; idx < 16384; idx += MLP_THREADS) {
        int k = idx >> 7, c = idx & 127;
        sm[OFF_WT + (c * 64 + ((k >> 1) ^ ((c >> 2) & 7))) * 2 + (k & 1)] = W3[idx];
    }
    __syncthreads();
    gemm_layer<1>(B64, sm + OFF_A, Wt64, sm + OFF_B3, n0, nullptr);
    __syncthreads();

    // ---- layer C: Wt <- W4^T ----
    for (int idx = t; idx < 16384; idx += MLP_THREADS) {
        int k = idx >> 7, c = idx & 127;
        sm[OFF_WT + (c * 64 + ((k >> 1) ^ ((c >> 2) & 7))) * 2 + (k & 1)] = W4[idx];
    }
    __syncthreads();
    gemm_layer<1>(A64, sm + OFF_B, Wt64, sm + OFF_B4, n0, nullptr);
    __syncthreads();

    // ---- W5 + rotation epilogue: one thread per node ----
    if (t < NT) {
        int gnode = n0 + t;
        if (gnode < NODES) {
            int sw = (t >> 3) & 3;
            const u64* Pp = B64 + t * 64;
            u64 sj2[6];
#pragma unroll
            for (int j = 0; j < 6; j++) sj2[j] = 0ull;
#pragma unroll 8
            for (int kp = 0; kp < 64; kp++) {
                u64 x2 = Pp[kp ^ sw];
#pragma unroll
                for (int j = 0; j < 6; j++) {
                    u64 w2 = *(const u64*)&sm[OFF_W5T + j * 128 + 2 * kp];
                    sj2[j] = fma2(x2, w2, sj2[j]);
                }
            }
            float pred[6];
#pragma unroll
            for (int j = 0; j < 6; j++) {
                float lo, hi;
                unpack2(sj2[j], lo, hi);
                pred[j] = lo + hi + sm[OFF_B5 + j];
            }
            const float* R = g_R + (size_t)gnode * 9;
            float Rl[9];
#pragma unroll
            for (int i = 0; i < 9; i++) Rl[i] = R[i];
            const float* xin = inp + (size_t)gnode * 6;
            float* xout = out + (size_t)gnode * 6;
#pragma unroll
            for (int j = 0; j < 6; j++) {
                int i = j % 3, off = (j / 3) * 3;
                float gl = Rl[i * 3 + 0] * pred[off + 0]
                         + Rl[i * 3 + 1] * pred[off + 1]
                         + Rl[i * 3 + 2] * pred[off + 2];
                xout[j] = xin[j] + gl;
            }
        }
    }
}

// ---------------------------------------------------------------------------
extern "C" void kernel_launch(void* const* d_in, const int* in_sizes, int n_in,
                              void* d_out, int out_size)
{
    const float* inp = (const float*)d_in[0];
    const float* W1  = (const float*)d_in[1];
    const float* b1  = (const float*)d_in[2];
    const float* W2  = (const float*)d_in[3];
    const float* b2  = (const float*)d_in[4];
    const float* Wr  = (const float*)d_in[5];
    const float* br  = (const float*)d_in[6];
    const float* W3  = (const float*)d_in[7];
    const float* b3  = (const float*)d_in[8];
    const float* W4  = (const float*)d_in[9];
    const float* b4  = (const float*)d_in[10];
    const float* W5  = (const float*)d_in[11];
    const float* b5  = (const float*)d_in[12];
    float* out = (float*)d_out;

    const int SMEM3 = SMEM_FL * 4;   // ~170 KB dynamic smem
    cudaFuncSetAttribute(node_mlp_kernel,
                         cudaFuncAttributeMaxDynamicSharedMemorySize, SMEM3);

    node_pre_kernel<<<NODES / 128, 128>>>(inp);
    edge_agg_kernel<<<NODES, 64>>>(inp, W1, b1);
    node_mlp_kernel<<<MLP_BLOCKS, MLP_THREADS, SMEM3>>>(inp, W2, b2, Wr, br,
                                                        W3, b3, W4, b4, W5, b5, out);
}

// round 7
// speedup vs baseline: 2.8735x; 1.0063x over previous
#include <cuda_runtime.h>
#include <math.h>

#define BB 128
#define NN 100
#define HH 128
#define NODES (BB*NN)          // 12800
#define NODES_PAD 12864        // 134 blocks * 96 nodes
#define PI_F 3.14159265358979323846f
#define EPS_F 1e-7f

// Scratch (allocation-free rule: device globals; BSS zero-init covers padding)
__device__ float g_R[NODES_PAD * 9];
__device__ float g_cv[NODES_PAD * 3];
__device__ float g_hacc[NODES_PAD * HH];

typedef unsigned long long u64;

// ---- packed f32x2 helpers -------------------------------------------------
__device__ __forceinline__ u64 fma2(u64 a, u64 b, u64 c) {
    u64 d;
    asm("fma.rn.f32x2 %0, %1, %2, %3;" : "=l"(d) : "l"(a), "l"(b), "l"(c));
    return d;
}
__device__ __forceinline__ u64 mul2(u64 a, u64 b) {
    u64 d; asm("mul.rn.f32x2 %0, %1, %2;" : "=l"(d) : "l"(a), "l"(b)); return d;
}
__device__ __forceinline__ u64 add2(u64 a, u64 b) {
    u64 d; asm("add.rn.f32x2 %0, %1, %2;" : "=l"(d) : "l"(a), "l"(b)); return d;
}
__device__ __forceinline__ u64 pack2(float lo, float hi) {
    u64 d; asm("mov.b64 %0, {%1, %2};" : "=l"(d) : "f"(lo), "f"(hi)); return d;
}
__device__ __forceinline__ void unpack2(u64 v, float& lo, float& hi) {
    asm("mov.b64 {%0, %1}, %2;" : "=f"(lo), "=f"(hi) : "l"(v));
}
__device__ __forceinline__ float tanh_fast(float x) {
    float r; asm("tanh.approx.f32 %0, %1;" : "=f"(r) : "f"(x)); return r;
}

__device__ __forceinline__ void vel_to_R(float vx, float vy, float vz, float* R) {
    float rho = sqrtf(vx * vx + vy * vy + vz * vz);
    float theta = atan2f(vy, vx);
    if (theta < 0.0f) theta += 2.0f * PI_F;
    float c = vz / (rho + EPS_F);
    c = fminf(fmaxf(c, -1.0f), 1.0f);
    float phi = acosf(c);
    float st, ct, sp, cp;
    sincosf(theta, &st, &ct);
    sincosf(phi, &sp, &cp);
    R[0] = cp * ct; R[1] = -st;  R[2] = sp * ct;
    R[3] = cp * st; R[4] = ct;   R[5] = sp * st;
    R[6] = -sp;     R[7] = 0.0f; R[8] = cp;
}

// ---------------------------------------------------------------------------
// Kernel 1: per-node rotation matrix + canonical velocity
// ---------------------------------------------------------------------------
__global__ void node_pre_kernel(const float* __restrict__ inp) {
    int idx = blockIdx.x * 128 + threadIdx.x;
    if (idx >= NODES) return;
    const float* v = inp + (size_t)idx * 6 + 3;
    float vx = v[0], vy = v[1], vz = v[2];
    float R[9];
    vel_to_R(vx, vy, vz, R);
#pragma unroll
    for (int i = 0; i < 9; i++) g_R[idx * 9 + i] = R[i];
    g_cv[idx * 3 + 0] = R[0] * vx + R[3] * vy + R[6] * vz;
    g_cv[idx * 3 + 1] = R[1] * vx + R[4] * vy + R[7] * vz;
    g_cv[idx * 3 + 2] = R[2] * vx + R[5] * vy + R[8] * vz;
}

// ---------------------------------------------------------------------------
// Kernel 2: per (b, recv) block of 64 threads; each thread owns TWO hidden
// channels (t, t+64). Edge features paired in smem; pair 49 .y slot is zeroed
// and its spurious silu(base) contribution subtracted analytically.
// hacc[c] = sum_e silu(ea_e @ W1)_c   (W2 deferred by linearity)
// ---------------------------------------------------------------------------
__global__ __launch_bounds__(64) void edge_agg_kernel(
    const float* __restrict__ inp,
    const float* __restrict__ W1,
    const float* __restrict__ b1)
{
    __shared__ __align__(16) float2 ea2[50][12];
    int b = blockIdx.x / NN;
    int r = blockIdx.x % NN;
    int t = threadIdx.x;          // 0..63
    int node_r = b * NN + r;

    // packed weights for channels t and t+64 (varying rows 0..11)
    u64 wa[12], wb[12];
#pragma unroll
    for (int k = 0; k < 12; k++) {
        float x = W1[k * HH + t];
        float y = W1[k * HH + t + 64];
        wa[k] = pack2(x, x);
        wb[k] = pack2(y, y);
    }

    float cv0 = g_cv[node_r * 3 + 0];
    float cv1 = g_cv[node_r * 3 + 1];
    float cv2 = g_cv[node_r * 3 + 2];
    float baseA = b1[t]      + cv0 * W1[15 * HH + t]      + cv1 * W1[16 * HH + t]      + cv2 * W1[17 * HH + t];
    float baseB = b1[t + 64] + cv0 * W1[15 * HH + t + 64] + cv1 * W1[16 * HH + t + 64] + cv2 * W1[17 * HH + t + 64];
    u64 base2A = pack2(baseA, baseA);
    u64 base2B = pack2(baseB, baseB);

    // build edge features: thread t handles edges t and t+64 (if <99)
    {
        float Rr[9];
#pragma unroll
        for (int i = 0; i < 9; i++) Rr[i] = g_R[node_r * 9 + i];
        const float* xi = inp + (size_t)node_r * 6;
        float xi0 = xi[0], xi1 = xi[1], xi2 = xi[2];

        for (int e = t; e < NN - 1; e += 64) {
            int s = e + (e >= r ? 1 : 0);
            int node_s = b * NN + s;
            const float* xj = inp + (size_t)node_s * 6;
            float Rs[9];
#pragma unroll
            for (int i = 0; i < 9; i++) Rs[i] = g_R[node_s * 9 + i];

            float rel0 = xj[0] - xi0, rel1 = xj[1] - xi1, rel2 = xj[2] - xi2;
            float rr0 = Rr[0] * rel0 + Rr[3] * rel1 + Rr[6] * rel2;
            float rr1 = Rr[1] * rel0 + Rr[4] * rel1 + Rr[7] * rel2;
            float rr2 = Rr[2] * rel0 + Rr[5] * rel1 + Rr[8] * rel2;
            float ro00 = Rr[0] * Rs[0] + Rr[3] * Rs[3] + Rr[6] * Rs[6];
            float ro10 = Rr[1] * Rs[0] + Rr[4] * Rs[3] + Rr[7] * Rs[6];
            float ro20 = Rr[2] * Rs[0] + Rr[5] * Rs[3] + Rr[8] * Rs[6];
            float ro21 = Rr[2] * Rs[1] + Rr[5] * Rs[4] + Rr[8] * Rs[7];
            float ro22 = Rr[2] * Rs[2] + Rr[5] * Rs[5] + Rr[8] * Rs[8];

            float f[12];
            f[0] = rr0; f[1] = rr1; f[2] = rr2;
            f[3] = atan2f(ro10, ro00) * (1.0f / PI_F);
            float sa = fminf(fmaxf(-ro20, -1.0f), 1.0f);
            f[4] = asinf(sa) * (1.0f / PI_F);
            f[5] = atan2f(ro21, ro22) * (1.0f / PI_F);
            f[6] = sqrtf(rel0 * rel0 + rel1 * rel1 + rel2 * rel2);
            f[7] = atan2f(rr1, rr0);
            float rho_e = sqrtf(rr0 * rr0 + rr1 * rr1 + rr2 * rr2);
            float cc = rr2 / (rho_e + EPS_F);
            cc = fminf(fmaxf(cc, -1.0f), 1.0f);
            f[8] = acosf(cc);
            float vj0 = xj[3], vj1 = xj[4], vj2 = xj[5];
            f[9]  = Rr[0] * vj0 + Rr[3] * vj1 + Rr[6] * vj2;
            f[10] = Rr[1] * vj0 + Rr[4] * vj1 + Rr[7] * vj2;
            f[11] = Rr[2] * vj0 + Rr[5] * vj1 + Rr[8] * vj2;

            float* dst = (float*)&ea2[e >> 1][0];
            int u = e & 1;
#pragma unroll
            for (int k = 0; k < 12; k++) dst[2 * k + u] = f[k];
        }
    }
    // zero pair 49's .y lane (edge count 99 is odd)
    if (t == 63) {
        float* dst = (float*)&ea2[49][0];
#pragma unroll
        for (int k = 0; k < 12; k++) dst[2 * k + 1] = 0.0f;
    }
    __syncthreads();

    const u64 HALF2 = pack2(0.5f, 0.5f);
    u64 accMA = 0ull, accTA = 0ull, accMB = 0ull, accTB = 0ull;
#pragma unroll 5
    for (int p = 0; p < 50; p++) {
        const ulonglong2* q = (const ulonglong2*)&ea2[p][0];
        ulonglong2 c0 = q[0], c1 = q[1], c2 = q[2];
        u64 aA = base2A, aB = base2B;
        aA = fma2(c0.x, wa[0], aA);  aB = fma2(c0.x, wb[0], aB);
        aA = fma2(c0.y, wa[1], aA);  aB = fma2(c0.y, wb[1], aB);
        aA = fma2(c1.x, wa[2], aA);  aB = fma2(c1.x, wb[2], aB);
        aA = fma2(c1.y, wa[3], aA);  aB = fma2(c1.y, wb[3], aB);
        aA = fma2(c2.x, wa[4], aA);  aB = fma2(c2.x, wb[4], aB);
        aA = fma2(c2.y, wa[5], aA);  aB = fma2(c2.y, wb[5], aB);
        ulonglong2 c3 = q[3], c4 = q[4], c5 = q[5];
        aA = fma2(c3.x, wa[6], aA);  aB = fma2(c3.x, wb[6], aB);
        aA = fma2(c3.y, wa[7], aA);  aB = fma2(c3.y, wb[7], aB);
        aA = fma2(c4.x, wa[8], aA);  aB = fma2(c4.x, wb[8], aB);
        aA = fma2(c4.y, wa[9], aA);  aB = fma2(c4.y, wb[9], aB);
        aA = fma2(c5.x, wa[10], aA); aB = fma2(c5.x, wb[10], aB);
        aA = fma2(c5.y, wa[11], aA); aB = fma2(c5.y, wb[11], aB);

        // silu(a) = m + m*tanh(m), m = a/2; accumulate Sum(m) and Sum(m*t)
        u64 mA = mul2(aA, HALF2);
        u64 mB = mul2(aB, HALF2);
        float ml, mh;
        unpack2(mA, ml, mh);
        u64 tA = pack2(tanh_fast(ml), tanh_fast(mh));
        unpack2(mB, ml, mh);
        u64 tB = pack2(tanh_fast(ml), tanh_fast(mh));
        accMA = add2(accMA, mA);  accTA = fma2(mA, tA, accTA);
        accMB = add2(accMB, mB);  accTB = fma2(mB, tB, accTB);
    }

    // remove the padded lane's silu(base) and store
    {
        float m0, m1, s0, s1;
        unpack2(accMA, m0, m1); unpack2(accTA, s0, s1);
        float mb = 0.5f * baseA;
        float corr = fmaf(mb, tanh_fast(mb), mb);
        g_hacc[(size_t)node_r * HH + t] = (m0 + m1 + s0 + s1) - corr;

        unpack2(accMB, m0, m1); unpack2(accTB, s0, s1);
        mb = 0.5f * baseB;
        corr = fmaf(mb, tanh_fast(mb), mb);
        g_hacc[(size_t)node_r * HH + t + 64] = (m0 + m1 + s0 + s1) - corr;
    }
}

// ---------------------------------------------------------------------------
// Kernel 3: register-tiled GEMM MLP. 134 blocks x 384 threads; block owns 96
// nodes through all layers. Per layer: stage W transposed+swizzled in smem,
// GEMM 96x128 with warp-tile 32x32, thread micro-tile 8 nodes x 4 channels,
// k-pair-packed FFMA2. XOR swizzle keeps LDS.64 conflict-free.
// ---------------------------------------------------------------------------
#define MLP_BLOCKS 134
#define MLP_THREADS 384
#define NT 96

// smem float offsets
#define OFF_WT  0         // 16384  (Wt64: 128 ch x 64 u64)
#define OFF_A   16384     // 12288  (A64: 96 nodes x 64 u64)
#define OFF_B   28672     // 12288
#define OFF_W5T 40960     // 768  (W5t[j][k], stride 128)
#define OFF_WR  41728     // 384  (Wr rows 3..5)
#define OFF_B2R 42112     // 128  (b2+br)
#define OFF_B3  42240
#define OFF_B4  42368
#define OFF_B5  42496     // 8
#define SMEM_FL 42504

// A-buffer float index for (local node n, feature k)
__device__ __forceinline__ int a_fidx(int n, int k) {
    return (n * 64 + ((k >> 1) ^ ((n >> 3) & 3))) * 2 + (k & 1);
}

template <int MODE>   // 0: layer A (bias b2+br + cv@Wr, no act), 1: relu+bias
__device__ __forceinline__ void gemm_layer(
    const u64* __restrict__ Ain, float* __restrict__ Bout,
    const u64* __restrict__ Wt, const float* __restrict__ bias,
    int n0, const float* __restrict__ wrS)
{
    int t = threadIdx.x;
    int warp = t >> 5, lane = t & 31;
    int wr = warp >> 2, wc = warp & 3;       // 3 x 4 warp tiles
    int ng = lane >> 3, cg = lane & 7;
    int nb = wr * 32 + ng * 8;               // node base (8 nodes)
    int cb = wc * 32 + cg * 4;               // channel base (4 channels)
    int swzx = (nb >> 3) & 3;
    int swzw = cg;                           // (cb>>2)&7

    const u64* Ap = Ain + nb * 64;
    const u64* Wp = Wt + cb * 64;

    u64 acc[8][4];
#pragma unroll
    for (int i = 0; i < 8; i++)
#pragma unroll
        for (int j = 0; j < 4; j++) acc[i][j] = 0ull;

#pragma unroll 4
    for (int kp = 0; kp < 64; kp++) {
        int ox = kp ^ swzx;
        int ow = kp ^ swzw;
        u64 xr[8], wv[4];
#pragma unroll
        for (int i = 0; i < 8; i++) xr[i] = Ap[i * 64 + ox];
#pragma unroll
        for (int j = 0; j < 4; j++) wv[j] = Wp[j * 64 + ow];
#pragma unroll
        for (int i = 0; i < 8; i++)
#pragma unroll
            for (int j = 0; j < 4; j++) acc[i][j] = fma2(xr[i], wv[j], acc[i][j]);
    }

#pragma unroll
    for (int i = 0; i < 8; i++) {
        int n = nb + i;
        int sw = (n >> 3) & 3;
        float cvx = 0.f, cvy = 0.f, cvz = 0.f;
        if (MODE == 0) {
            int gn = n0 + n;
            cvx = g_cv[gn * 3 + 0]; cvy = g_cv[gn * 3 + 1]; cvz = g_cv[gn * 3 + 2];
        }
#pragma unroll
        for (int j = 0; j < 4; j++) {
            int c = cb + j;
            float lo, hi;
            unpack2(acc[i][j], lo, hi);
            float s = lo + hi + bias[c];
            if (MODE == 0) {
                s += cvx * wrS[c] + cvy * wrS[128 + c] + cvz * wrS[256 + c];
            } else {
                s = fmaxf(s, 0.0f);
            }
            Bout[(n * 64 + ((c >> 1) ^ sw)) * 2 + (c & 1)] = s;
        }
    }
}

__global__ __launch_bounds__(MLP_THREADS, 1) void node_mlp_kernel(
    const float* __restrict__ inp,
    const float* __restrict__ W2, const float* __restrict__ b2,
    const float* __restrict__ Wr, const float* __restrict__ br,
    const float* __restrict__ W3, const float* __restrict__ b3,
    const float* __restrict__ W4, const float* __restrict__ b4,
    const float* __restrict__ W5, const float* __restrict__ b5,
    float* __restrict__ out)
{
    extern __shared__ float sm[];
    int t = threadIdx.x;
    int n0 = blockIdx.x * NT;
    const float inv99 = 1.0f / 99.0f;

    // one-time stages: A0 (h/99), small weights, biases
    for (int idx = t; idx < NT * 128; idx += MLP_THREADS) {
        int n = idx >> 7, k = idx & 127;
        sm[OFF_A + a_fidx(n, k)] = g_hacc[(size_t)(n0 + n) * 128 + k] * inv99;
    }
    for (int idx = t; idx < 768; idx += MLP_THREADS) {
        int k = idx / 6, j = idx % 6;
        sm[OFF_W5T + j * 128 + k] = W5[idx];
    }
    for (int idx = t; idx < 384; idx += MLP_THREADS) sm[OFF_WR + idx] = Wr[384 + idx];
    if (t < 128) {
        sm[OFF_B2R + t] = b2[t] + br[t];
        sm[OFF_B3 + t] = b3[t];
        sm[OFF_B4 + t] = b4[t];
    }
    if (t < 6) sm[OFF_B5 + t] = b5[t];

    u64* A64 = (u64*)(sm + OFF_A);
    u64* B64 = (u64*)(sm + OFF_B);
    u64* Wt64 = (u64*)(sm + OFF_WT);

    // ---- layer A: Wt <- W2^T ----
    for (int idx = t; idx < 16384; idx += MLP_THREADS) {
        int k = idx >> 7, c = idx & 127;
        sm[OFF_WT + (c * 64 + ((k >> 1) ^ ((c >> 2) & 7))) * 2 + (k & 1)] = W2[idx];
    }
    __syncthreads();
    gemm_layer<0>(A64, sm + OFF_B, Wt64, sm + OFF_B2R, n0, sm + OFF_WR);
    __syncthreads();

    // ---- layer B: Wt <- W3^T ----
    for (int idx = t; idx < 16384; idx += MLP_THREADS) {
        int k = idx >> 7, c = idx & 127;
        sm[OFF_WT + (c * 64 + ((k >> 1) ^ ((c >> 2) & 7))) * 2 + (k & 1)] = W3[idx];
    }
    __syncthreads();
    gemm_layer<1>(B64, sm + OFF_A, Wt64, sm + OFF_B3, n0, nullptr);
    __syncthreads();

    // ---- layer C: Wt <- W4^T ----
    for (int idx = t; idx < 16384; idx += MLP_THREADS) {
        int k = idx >> 7, c = idx & 127;
        sm[OFF_WT + (c * 64 + ((k >> 1) ^ ((c >> 2) & 7))) * 2 + (k & 1)] = W4[idx];
    }
    __syncthreads();
    gemm_layer<1>(A64, sm + OFF_B, Wt64, sm + OFF_B4, n0, nullptr);
    __syncthreads();

    // ---- W5 + rotation epilogue: one thread per node ----
    if (t < NT) {
        int gnode = n0 + t;
        if (gnode < NODES) {
            int sw = (t >> 3) & 3;
            const u64* Pp = B64 + t * 64;
            u64 sj2[6];
#pragma unroll
            for (int j = 0; j < 6; j++) sj2[j] = 0ull;
#pragma unroll 8
            for (int kp = 0; kp < 64; kp++) {
                u64 x2 = Pp[kp ^ sw];
#pragma unroll
                for (int j = 0; j < 6; j++) {
                    u64 w2 = *(const u64*)&sm[OFF_W5T + j * 128 + 2 * kp];
                    sj2[j] = fma2(x2, w2, sj2[j]);
                }
            }
            float pred[6];
#pragma unroll
            for (int j = 0; j < 6; j++) {
                float lo, hi;
                unpack2(sj2[j], lo, hi);
                pred[j] = lo + hi + sm[OFF_B5 + j];
            }
            const float* R = g_R + (size_t)gnode * 9;
            float Rl[9];
#pragma unroll
            for (int i = 0; i < 9; i++) Rl[i] = R[i];
            const float* xin = inp + (size_t)gnode * 6;
            float* xout = out + (size_t)gnode * 6;
#pragma unroll
            for (int j = 0; j < 6; j++) {
                int i = j % 3, off = (j / 3) * 3;
                float gl = Rl[i * 3 + 0] * pred[off + 0]
                         + Rl[i * 3 + 1] * pred[off + 1]
                         + Rl[i * 3 + 2] * pred[off + 2];
                xout[j] = xin[j] + gl;
            }
        }
    }
}

// ---------------------------------------------------------------------------
extern "C" void kernel_launch(void* const* d_in, const int* in_sizes, int n_in,
                              void* d_out, int out_size)
{
    const float* inp = (const float*)d_in[0];
    const float* W1  = (const float*)d_in[1];
    const float* b1  = (const float*)d_in[2];
    const float* W2  = (const float*)d_in[3];
    const float* b2  = (const float*)d_in[4];
    const float* Wr  = (const float*)d_in[5];
    const float* br  = (const float*)d_in[6];
    const float* W3  = (const float*)d_in[7];
    const float* b3  = (const float*)d_in[8];
    const float* W4  = (const float*)d_in[9];
    const float* b4  = (const float*)d_in[10];
    const float* W5  = (const float*)d_in[11];
    const float* b5  = (const float*)d_in[12];
    float* out = (float*)d_out;

    const int SMEM3 = SMEM_FL * 4;   // ~170 KB dynamic smem
    cudaFuncSetAttribute(node_mlp_kernel,
                         cudaFuncAttributeMaxDynamicSharedMemorySize, SMEM3);

    node_pre_kernel<<<NODES / 128, 128>>>(inp);
    edge_agg_kernel<<<NODES, 64>>>(inp, W1, b1);
    node_mlp_kernel<<<MLP_BLOCKS, MLP_THREADS, SMEM3>>>(inp, W2, b2, Wr, br,
                                                        W3, b3, W4, b4, W5, b5, out);
}

// round 10
// speedup vs baseline: 3.1492x; 1.0959x over previous
#include <cuda_runtime.h>
#include <math.h>
#include <stdint.h>

#define BB 128
#define NN 100
#define HH 128
#define NODES (BB*NN)          // 12800
#define NODES_PAD 12864
#define PI_F 3.14159265358979323846f
#define EPS_F 1e-7f

__device__ float g_R[NODES_PAD * 9];
__device__ float g_cv[NODES_PAD * 3];
__device__ float g_hacc[NODES_PAD * HH];

typedef unsigned long long u64;

// ---- packed f32x2 helpers (FFMA2, for the MLP kernel) ---------------------
__device__ __forceinline__ u64 fma2(u64 a, u64 b, u64 c) {
    u64 d;
    asm("fma.rn.f32x2 %0, %1, %2, %3;" : "=l"(d) : "l"(a), "l"(b), "l"(c));
    return d;
}
__device__ __forceinline__ u64 pack2(float lo, float hi) {
    u64 d; asm("mov.b64 %0, {%1, %2};" : "=l"(d) : "f"(lo), "f"(hi)); return d;
}
__device__ __forceinline__ void unpack2(u64 v, float& lo, float& hi) {
    asm("mov.b64 {%0, %1}, %2;" : "=f"(lo), "=f"(hi) : "l"(v));
}
__device__ __forceinline__ float tanh_fast(float x) {
    float r; asm("tanh.approx.f32 %0, %1;" : "=f"(r) : "f"(x)); return r;
}
__device__ __forceinline__ uint32_t bf16_rn_bits(float f) {
    uint32_t u = __float_as_uint(f);
    return (u + 0x7FFFu + ((u >> 16) & 1u)) & 0xFFFF0000u;
}
// pack two bf16 (given as top-16 bits of u32) into one .b32: elem0 in LSBs
__device__ __forceinline__ uint32_t bfpair(uint32_t h0, uint32_t h1) {
    return (h0 >> 16) | (h1 & 0xFFFF0000u);
}
__device__ __forceinline__ void split2(float v, uint32_t& hi, uint32_t& lo) {
    hi = bf16_rn_bits(v);
    lo = bf16_rn_bits(v - __uint_as_float(hi));
}

// mma.sync m16n8k16 row.col bf16 -> f32 accumulate (PTX ISA 7.0, sm_80+)
__device__ __forceinline__ void mma_bf16(float* d, const uint32_t* a,
                                         uint32_t b0, uint32_t b1) {
    asm volatile(
        "mma.sync.aligned.m16n8k16.row.col.f32.bf16.bf16.f32 "
        "{%0,%1,%2,%3}, {%4,%5,%6,%7}, {%8,%9}, {%0,%1,%2,%3};"
        : "+f"(d[0]), "+f"(d[1]), "+f"(d[2]), "+f"(d[3])
        : "r"(a[0]), "r"(a[1]), "r"(a[2]), "r"(a[3]), "r"(b0), "r"(b1));
}

__device__ __forceinline__ void vel_to_R(float vx, float vy, float vz, float* R) {
    float rho = sqrtf(vx * vx + vy * vy + vz * vz);
    float theta = atan2f(vy, vx);
    if (theta < 0.0f) theta += 2.0f * PI_F;
    float c = vz / (rho + EPS_F);
    c = fminf(fmaxf(c, -1.0f), 1.0f);
    float phi = acosf(c);
    float st, ct, sp, cp;
    sincosf(theta, &st, &ct);
    sincosf(phi, &sp, &cp);
    R[0] = cp * ct; R[1] = -st;  R[2] = sp * ct;
    R[3] = cp * st; R[4] = ct;   R[5] = sp * st;
    R[6] = -sp;     R[7] = 0.0f; R[8] = cp;
}

// ---------------------------------------------------------------------------
// Kernel 1: per-node rotation matrix + canonical velocity
// ---------------------------------------------------------------------------
__global__ void node_pre_kernel(const float* __restrict__ inp) {
    int idx = blockIdx.x * 128 + threadIdx.x;
    if (idx >= NODES) return;
    const float* v = inp + (size_t)idx * 6 + 3;
    float vx = v[0], vy = v[1], vz = v[2];
    float R[9];
    vel_to_R(vx, vy, vz, R);
#pragma unroll
    for (int i = 0; i < 9; i++) g_R[idx * 9 + i] = R[i];
    g_cv[idx * 3 + 0] = R[0] * vx + R[3] * vy + R[6] * vz;
    g_cv[idx * 3 + 1] = R[1] * vx + R[4] * vy + R[7] * vz;
    g_cv[idx * 3 + 2] = R[2] * vx + R[5] * vy + R[8] * vz;
}

// ---------------------------------------------------------------------------
// Kernel 2: edge aggregation via legacy mma.sync (HMMA), bf16 split-2.
// Block = 128 threads (4 warps), handles ENODES_PER_BLK nodes sequentially.
// Warp w owns channels [w*32, w*32+32) as two m16 tiles; A = 0.5*W1^T frags
// built once (registers, persist across nodes). Per node: threads 0..98 build
// the 12 edge features -> smem bf16 hi/lo [104 rows x stride 9 words]; then
// 13 n-tiles x (3 split MMAs x 2 m-tiles); silu+rowsum epilogue on fragments.
// ---------------------------------------------------------------------------
#define EBLOCKS 1280
#define ENODES_PER_BLK 10     // 1280*10 = 12800
#define FSTRIDE 9             // u32 words per edge row (16 bf16 + pad)

__global__ __launch_bounds__(128) void edge_hmma_kernel(
    const float* __restrict__ inp,
    const float* __restrict__ W1,
    const float* __restrict__ b1)
{
    __shared__ uint32_t feat_hi[104 * FSTRIDE];
    __shared__ uint32_t feat_lo[104 * FSTRIDE];

    int t = threadIdx.x;
    int w = t >> 5;
    int lane = t & 31;
    int g = lane >> 2;        // 0..7
    int t4 = lane & 3;        // 0..3

    // zero feature arrays once (covers k-pad words and edge rows 99..103)
    for (int i = t; i < 104 * FSTRIDE; i += 128) {
        feat_hi[i] = 0u;
        feat_lo[i] = 0u;
    }

    // ---- A fragments: 0.5*W1^T, rows = channels, cols = k (12 real, pad 0)
    uint32_t Ahi[2][4], Alo[2][4];
#pragma unroll
    for (int mt = 0; mt < 2; mt++) {
        int r0 = w * 32 + mt * 16 + g;
        int r1 = r0 + 8;
        int c0 = 2 * t4;          // k cols c0, c0+1 (<8)
        int c2 = c0 + 8;          // k cols c2, c2+1 (8..15; >=12 -> 0)
        float v00 = 0.5f * W1[c0 * HH + r0];
        float v01 = 0.5f * W1[(c0 + 1) * HH + r0];
        float v10 = 0.5f * W1[c0 * HH + r1];
        float v11 = 0.5f * W1[(c0 + 1) * HH + r1];
        float v02 = (c2     < 12) ? 0.5f * W1[c2 * HH + r0]       : 0.0f;
        float v03 = (c2 + 1 < 12) ? 0.5f * W1[(c2 + 1) * HH + r0] : 0.0f;
        float v12 = (c2     < 12) ? 0.5f * W1[c2 * HH + r1]       : 0.0f;
        float v13 = (c2 + 1 < 12) ? 0.5f * W1[(c2 + 1) * HH + r1] : 0.0f;
        uint32_t h0, l0, h1, l1;
        split2(v00, h0, l0); split2(v01, h1, l1);
        Ahi[mt][0] = bfpair(h0, h1); Alo[mt][0] = bfpair(l0, l1);
        split2(v10, h0, l0); split2(v11, h1, l1);
        Ahi[mt][1] = bfpair(h0, h1); Alo[mt][1] = bfpair(l0, l1);
        split2(v02, h0, l0); split2(v03, h1, l1);
        Ahi[mt][2] = bfpair(h0, h1); Alo[mt][2] = bfpair(l0, l1);
        split2(v12, h0, l0); split2(v13, h1, l1);
        Ahi[mt][3] = bfpair(h0, h1); Alo[mt][3] = bfpair(l0, l1);
    }

    // per-thread channel constants for base term (4 rows: g, g+8, g+16, g+24)
    float b0h[4], w15[4], w16[4], w17[4];
#pragma unroll
    for (int i = 0; i < 4; i++) {
        int ch = w * 32 + i * 8 + g;
        b0h[i] = 0.5f * b1[ch];
        w15[i] = 0.5f * W1[15 * HH + ch];
        w16[i] = 0.5f * W1[16 * HH + ch];
        w17[i] = 0.5f * W1[17 * HH + ch];
    }
    __syncthreads();   // zero-phase complete before first build

    for (int ni = 0; ni < ENODES_PER_BLK; ni++) {
        int node = blockIdx.x * ENODES_PER_BLK + ni;

        // ---- build edge features (threads 0..98), bf16 hi/lo -> smem ----
        if (t < NN - 1) {
            int r_local = node % NN;
            int s = t + (t >= r_local ? 1 : 0);
            int node_s = node - r_local + s;
            const float* xj = inp + (size_t)node_s * 6;
            const float* xi = inp + (size_t)node * 6;
            float Rr[9], Rs[9];
#pragma unroll
            for (int i = 0; i < 9; i++) { Rr[i] = g_R[node * 9 + i]; Rs[i] = g_R[node_s * 9 + i]; }

            float rel0 = xj[0] - xi[0], rel1 = xj[1] - xi[1], rel2 = xj[2] - xi[2];
            float rr0 = Rr[0] * rel0 + Rr[3] * rel1 + Rr[6] * rel2;
            float rr1 = Rr[1] * rel0 + Rr[4] * rel1 + Rr[7] * rel2;
            float rr2 = Rr[2] * rel0 + Rr[5] * rel1 + Rr[8] * rel2;
            float ro00 = Rr[0] * Rs[0] + Rr[3] * Rs[3] + Rr[6] * Rs[6];
            float ro10 = Rr[1] * Rs[0] + Rr[4] * Rs[3] + Rr[7] * Rs[6];
            float ro20 = Rr[2] * Rs[0] + Rr[5] * Rs[3] + Rr[8] * Rs[6];
            float ro21 = Rr[2] * Rs[1] + Rr[5] * Rs[4] + Rr[8] * Rs[7];
            float ro22 = Rr[2] * Rs[2] + Rr[5] * Rs[5] + Rr[8] * Rs[8];

            float f[12];
            f[0] = rr0; f[1] = rr1; f[2] = rr2;
            f[3] = atan2f(ro10, ro00) * (1.0f / PI_F);
            float sa = fminf(fmaxf(-ro20, -1.0f), 1.0f);
            f[4] = asinf(sa) * (1.0f / PI_F);
            f[5] = atan2f(ro21, ro22) * (1.0f / PI_F);
            f[6] = sqrtf(rel0 * rel0 + rel1 * rel1 + rel2 * rel2);
            f[7] = atan2f(rr1, rr0);
            float rho_e = sqrtf(rr0 * rr0 + rr1 * rr1 + rr2 * rr2);
            float cc = rr2 / (rho_e + EPS_F);
            cc = fminf(fmaxf(cc, -1.0f), 1.0f);
            f[8] = acosf(cc);
            float vj0 = xj[3], vj1 = xj[4], vj2 = xj[5];
            f[9]  = Rr[0] * vj0 + Rr[3] * vj1 + Rr[6] * vj2;
            f[10] = Rr[1] * vj0 + Rr[4] * vj1 + Rr[7] * vj2;
            f[11] = Rr[2] * vj0 + Rr[5] * vj1 + Rr[8] * vj2;

            int rb = t * FSTRIDE;
#pragma unroll
            for (int k2 = 0; k2 < 6; k2++) {
                uint32_t h0, l0, h1, l1;
                split2(f[2 * k2], h0, l0);
                split2(f[2 * k2 + 1], h1, l1);
                feat_hi[rb + k2] = bfpair(h0, h1);
                feat_lo[rb + k2] = bfpair(l0, l1);
            }
        }
        __syncthreads();

        // ---- per-node base ----
        float cv0 = g_cv[node * 3], cv1 = g_cv[node * 3 + 1], cv2 = g_cv[node * 3 + 2];
        float base[4];
#pragma unroll
        for (int i = 0; i < 4; i++)
            base[i] = fmaf(cv2, w17[i], fmaf(cv1, w16[i], fmaf(cv0, w15[i], b0h[i])));

        float acc[4] = {0.f, 0.f, 0.f, 0.f};

        // ---- 13 n-tiles of 8 edges ----
#pragma unroll 1
        for (int nt = 0; nt < 13; nt++) {
            const uint32_t* fh = feat_hi + (nt * 8 + g) * FSTRIDE;
            const uint32_t* fl = feat_lo + (nt * 8 + g) * FSTRIDE;
            uint32_t bh0 = fh[t4],     bh1 = fh[4 + t4];
            uint32_t bl0 = fl[t4],     bl1 = fl[4 + t4];

            float d0[4] = {0.f, 0.f, 0.f, 0.f};
            float d1[4] = {0.f, 0.f, 0.f, 0.f};
            mma_bf16(d0, Ahi[0], bh0, bh1);
            mma_bf16(d0, Ahi[0], bl0, bl1);
            mma_bf16(d0, Alo[0], bh0, bh1);
            mma_bf16(d1, Ahi[1], bh0, bh1);
            mma_bf16(d1, Ahi[1], bl0, bl1);
            mma_bf16(d1, Alo[1], bh0, bh1);

            if (nt < 12) {
#pragma unroll
                for (int e = 0; e < 4; e++) {
                    int ri = e >> 1;
                    float m = d0[e] + base[ri];
                    acc[ri] = fmaf(m, tanh_fast(m), acc[ri] + m);
                    float m1 = d1[e] + base[2 + ri];
                    acc[2 + ri] = fmaf(m1, tanh_fast(m1), acc[2 + ri] + m1);
                }
            } else {
                // cols 96..103; only cols < 99 are real edges
#pragma unroll
                for (int e = 0; e < 4; e++) {
                    int ri = e >> 1;
                    float mask = (96 + 2 * t4 + (e & 1) < 99) ? 1.0f : 0.0f;
                    float m = d0[e] + base[ri];
                    acc[ri] += mask * fmaf(m, tanh_fast(m), m);
                    float m1 = d1[e] + base[2 + ri];
                    acc[2 + ri] += mask * fmaf(m1, tanh_fast(m1), m1);
                }
            }
        }

        // ---- reduce across the 4 lanes of each row-group, then store ----
#pragma unroll
        for (int i = 0; i < 4; i++) {
            acc[i] += __shfl_xor_sync(0xffffffffu, acc[i], 1);
            acc[i] += __shfl_xor_sync(0xffffffffu, acc[i], 2);
        }
        if (t4 == 0) {
            float* hp = &g_hacc[(size_t)node * HH + w * 32 + g];
            hp[0]  = acc[0];
            hp[8]  = acc[1];
            hp[16] = acc[2];
            hp[24] = acc[3];
        }
        __syncthreads();   // protect smem before next node's build
    }
}

// ---------------------------------------------------------------------------
// Kernel 3: register-tiled GEMM MLP (unchanged, proven)
// ---------------------------------------------------------------------------
#define MLP_BLOCKS 134
#define MLP_THREADS 384
#define NT 96
#define OFF_WT  0
#define OFF_A   16384
#define OFF_B   28672
#define OFF_W5T 40960
#define OFF_WR  41728
#define OFF_B2R 42112
#define OFF_B3  42240
#define OFF_B4  42368
#define OFF_B5  42496
#define SMEM_FL 42504

__device__ __forceinline__ int a_fidx(int n, int k) {
    return (n * 64 + ((k >> 1) ^ ((n >> 3) & 3))) * 2 + (k & 1);
}

template <int MODE>
__device__ __forceinline__ void gemm_layer(
    const u64* __restrict__ Ain, float* __restrict__ Bout,
    const u64* __restrict__ Wt, const float* __restrict__ bias,
    int n0, const float* __restrict__ wrS)
{
    int t = threadIdx.x;
    int warp = t >> 5, lane = t & 31;
    int wr = warp >> 2, wc = warp & 3;
    int ng = lane >> 3, cg = lane & 7;
    int nb = wr * 32 + ng * 8;
    int cb = wc * 32 + cg * 4;
    int swzx = (nb >> 3) & 3;
    int swzw = cg;

    const u64* Ap = Ain + nb * 64;
    const u64* Wp = Wt + cb * 64;

    u64 acc[8][4];
#pragma unroll
    for (int i = 0; i < 8; i++)
#pragma unroll
        for (int j = 0; j < 4; j++) acc[i][j] = 0ull;

#pragma unroll 4
    for (int kp = 0; kp < 64; kp++) {
        int ox = kp ^ swzx;
        int ow = kp ^ swzw;
        u64 xr[8], wv[4];
#pragma unroll
        for (int i = 0; i < 8; i++) xr[i] = Ap[i * 64 + ox];
#pragma unroll
        for (int j = 0; j < 4; j++) wv[j] = Wp[j * 64 + ow];
#pragma unroll
        for (int i = 0; i < 8; i++)
#pragma unroll
            for (int j = 0; j < 4; j++) acc[i][j] = fma2(xr[i], wv[j], acc[i][j]);
    }

#pragma unroll
    for (int i = 0; i < 8; i++) {
        int n = nb + i;
        int sw = (n >> 3) & 3;
        float cvx = 0.f, cvy = 0.f, cvz = 0.f;
        if (MODE == 0) {
            int gn = n0 + n;
            cvx = g_cv[gn * 3 + 0]; cvy = g_cv[gn * 3 + 1]; cvz = g_cv[gn * 3 + 2];
        }
#pragma unroll
        for (int j = 0; j < 4; j++) {
            int c = cb + j;
            float lo, hi;
            unpack2(acc[i][j], lo, hi);
            float s = lo + hi + bias[c];
            if (MODE == 0) s += cvx * wrS[c] + cvy * wrS[128 + c] + cvz * wrS[256 + c];
            else s = fmaxf(s, 0.0f);
            Bout[(n * 64 + ((c >> 1) ^ sw)) * 2 + (c & 1)] = s;
        }
    }
}

__global__ __launch_bounds__(MLP_THREADS, 1) void node_mlp_kernel(
    const float* __restrict__ inp,
    const float* __restrict__ W2, const float* __restrict__ b2,
    const float* __restrict__ Wr, const float* __restrict__ br,
    const float* __restrict__ W3, const float* __restrict__ b3,
    const float* __restrict__ W4, const float* __restrict__ b4,
    const float* __restrict__ W5, const float* __restrict__ b5,
    float* __restrict__ out)
{
    extern __shared__ float sm[];
    int t = threadIdx.x;
    int n0 = blockIdx.x * NT;
    const float inv99 = 1.0f / 99.0f;

    for (int idx = t; idx < NT * 128; idx += MLP_THREADS) {
        int n = idx >> 7, k = idx & 127;
        sm[OFF_A + a_fidx(n, k)] = g_hacc[(size_t)(n0 + n) * 128 + k] * inv99;
    }
    for (int idx = t; idx < 768; idx += MLP_THREADS) {
        int k = idx / 6, j = idx % 6;
        sm[OFF_W5T + j * 128 + k] = W5[idx];
    }
    for (int idx = t; idx < 384; idx += MLP_THREADS) sm[OFF_WR + idx] = Wr[384 + idx];
    if (t < 128) {
        sm[OFF_B2R + t] = b2[t] + br[t];
        sm[OFF_B3 + t] = b3[t];
        sm[OFF_B4 + t] = b4[t];
    }
    if (t < 6) sm[OFF_B5 + t] = b5[t];

    u64* A64 = (u64*)(sm + OFF_A);
    u64* B64 = (u64*)(sm + OFF_B);
    u64* Wt64 = (u64*)(sm + OFF_WT);

    for (int idx = t; idx < 16384; idx += MLP_THREADS) {
        int k = idx >> 7, c = idx & 127;
        sm[OFF_WT + (c * 64 + ((k >> 1) ^ ((c >> 2) & 7))) * 2 + (k & 1)] = W2[idx];
    }
    __syncthreads();
    gemm_layer<0>(A64, sm + OFF_B, Wt64, sm + OFF_B2R, n0, sm + OFF_WR);
    __syncthreads();

    for (int idx = t; idx < 16384; idx += MLP_THREADS) {
        int k = idx >> 7, c = idx & 127;
        sm[OFF_WT + (c * 64 + ((k >> 1) ^ ((c >> 2) & 7))) * 2 + (k & 1)] = W3[idx];
    }
    __syncthreads();
    gemm_layer<1>(B64, sm + OFF_A, Wt64, sm + OFF_B3, n0, nullptr);
    __syncthreads();

    for (int idx = t; idx < 16384; idx += MLP_THREADS) {
        int k = idx >> 7, c = idx & 127;
        sm[OFF_WT + (c * 64 + ((k >> 1) ^ ((c >> 2) & 7))) * 2 + (k & 1)] = W4[idx];
    }
    __syncthreads();
    gemm_layer<1>(A64, sm + OFF_B, Wt64, sm + OFF_B4, n0, nullptr);
    __syncthreads();

    if (t < NT) {
        int gnode = n0 + t;
        if (gnode < NODES) {
            int sw = (t >> 3) & 3;
            const u64* Pp = B64 + t * 64;
            u64 sj2[6];
#pragma unroll
            for (int j = 0; j < 6; j++) sj2[j] = 0ull;
#pragma unroll 8
            for (int kp = 0; kp < 64; kp++) {
                u64 x2 = Pp[kp ^ sw];
#pragma unroll
                for (int j = 0; j < 6; j++) {
                    u64 w2 = *(const u64*)&sm[OFF_W5T + j * 128 + 2 * kp];
                    sj2[j] = fma2(x2, w2, sj2[j]);
                }
            }
            float pred[6];
#pragma unroll
            for (int j = 0; j < 6; j++) {
                float lo, hi;
                unpack2(sj2[j], lo, hi);
                pred[j] = lo + hi + sm[OFF_B5 + j];
            }
            const float* R = g_R + (size_t)gnode * 9;
            float Rl[9];
#pragma unroll
            for (int i = 0; i < 9; i++) Rl[i] = R[i];
            const float* xin = inp + (size_t)gnode * 6;
            float* xout = out + (size_t)gnode * 6;
#pragma unroll
            for (int j = 0; j < 6; j++) {
                int i = j % 3, off = (j / 3) * 3;
                float gl = Rl[i * 3 + 0] * pred[off + 0]
                         + Rl[i * 3 + 1] * pred[off + 1]
                         + Rl[i * 3 + 2] * pred[off + 2];
                xout[j] = xin[j] + gl;
            }
        }
    }
}

// ---------------------------------------------------------------------------
extern "C" void kernel_launch(void* const* d_in, const int* in_sizes, int n_in,
                              void* d_out, int out_size)
{
    const float* inp = (const float*)d_in[0];
    const float* W1  = (const float*)d_in[1];
    const float* b1  = (const float*)d_in[2];
    const float* W2  = (const float*)d_in[3];
    const float* b2  = (const float*)d_in[4];
    const float* Wr  = (const float*)d_in[5];
    const float* br  = (const float*)d_in[6];
    const float* W3  = (const float*)d_in[7];
    const float* b3  = (const float*)d_in[8];
    const float* W4  = (const float*)d_in[9];
    const float* b4  = (const float*)d_in[10];
    const float* W5  = (const float*)d_in[11];
    const float* b5  = (const float*)d_in[12];
    float* out = (float*)d_out;

    const int SMEM3 = SMEM_FL * 4;
    cudaFuncSetAttribute(node_mlp_kernel,
                         cudaFuncAttributeMaxDynamicSharedMemorySize, SMEM3);

    node_pre_kernel<<<NODES / 128, 128>>>(inp);
    edge_hmma_kernel<<<EBLOCKS, 128>>>(inp, W1, b1);
    node_mlp_kernel<<<MLP_BLOCKS, MLP_THREADS, SMEM3>>>(inp, W2, b2, Wr, br,
                                                        W3, b3, W4, b4, W5, b5, out);
}

// round 11
// speedup vs baseline: 3.4395x; 1.0922x over previous
#include <cuda_runtime.h>
#include <cuda_fp16.h>
#include <math.h>
#include <stdint.h>

#define BB 128
#define NN 100
#define HH 128
#define NODES (BB*NN)          // 12800
#define NODES_PAD 12864
#define PI_F 3.14159265358979323846f
#define EPS_F 1e-7f

__device__ float g_R[NODES_PAD * 9];
__device__ float g_cv[NODES_PAD * 3];
__device__ float g_hacc[NODES_PAD * HH];

typedef unsigned long long u64;

// ---- packed f32x2 helpers -------------------------------------------------
__device__ __forceinline__ u64 fma2(u64 a, u64 b, u64 c) {
    u64 d;
    asm("fma.rn.f32x2 %0, %1, %2, %3;" : "=l"(d) : "l"(a), "l"(b), "l"(c));
    return d;
}
__device__ __forceinline__ u64 add2(u64 a, u64 b) {
    u64 d; asm("add.rn.f32x2 %0, %1, %2;" : "=l"(d) : "l"(a), "l"(b)); return d;
}
__device__ __forceinline__ u64 mul2(u64 a, u64 b) {
    u64 d; asm("mul.rn.f32x2 %0, %1, %2;" : "=l"(d) : "l"(a), "l"(b)); return d;
}
__device__ __forceinline__ u64 pack2(float lo, float hi) {
    u64 d; asm("mov.b64 %0, {%1, %2};" : "=l"(d) : "f"(lo), "f"(hi)); return d;
}
__device__ __forceinline__ u64 packu(uint32_t a, uint32_t b) {
    u64 d; asm("mov.b64 %0, {%1, %2};" : "=l"(d) : "r"(a), "r"(b)); return d;
}
__device__ __forceinline__ void unpack2(u64 v, float& lo, float& hi) {
    asm("mov.b64 {%0, %1}, %2;" : "=f"(lo), "=f"(hi) : "l"(v));
}
__device__ __forceinline__ float tanh_fast(float x) {
    float r; asm("tanh.approx.f32 %0, %1;" : "=f"(r) : "f"(x)); return r;
}
// pack two f32 -> f16x2 (lo in low half)
__device__ __forceinline__ uint32_t f16x2_pack(float lo, float hi) {
    uint32_t r;
    asm("cvt.rn.f16x2.f32 %0, %1, %2;" : "=r"(r) : "f"(hi), "f"(lo));
    return r;
}
// split a float into fp16 hi + fp16 residual (bit patterns)
__device__ __forceinline__ void splith(float v, uint32_t& h, uint32_t& l) {
    __half hh = __float2half_rn(v);
    float r = v - __half2float(hh);
    __half ll = __float2half_rn(r);
    h = (uint32_t)__half_as_ushort(hh);
    l = (uint32_t)__half_as_ushort(ll);
}
__device__ __forceinline__ uint32_t pkh(uint32_t a, uint32_t b) {  // a low, b high
    return a | (b << 16);
}

// mma.sync m16n8k16 row.col f16 -> f32 accumulate
__device__ __forceinline__ void mma_f16(float* d, const uint32_t* a,
                                        uint32_t b0, uint32_t b1) {
    asm volatile(
        "mma.sync.aligned.m16n8k16.row.col.f32.f16.f16.f32 "
        "{%0,%1,%2,%3}, {%4,%5,%6,%7}, {%8,%9}, {%0,%1,%2,%3};"
        : "+f"(d[0]), "+f"(d[1]), "+f"(d[2]), "+f"(d[3])
        : "r"(a[0]), "r"(a[1]), "r"(a[2]), "r"(a[3]), "r"(b0), "r"(b1));
}

__device__ __forceinline__ void vel_to_R(float vx, float vy, float vz, float* R) {
    float rho = sqrtf(vx * vx + vy * vy + vz * vz);
    float theta = atan2f(vy, vx);
    if (theta < 0.0f) theta += 2.0f * PI_F;
    float c = vz / (rho + EPS_F);
    c = fminf(fmaxf(c, -1.0f), 1.0f);
    float phi = acosf(c);
    float st, ct, sp, cp;
    sincosf(theta, &st, &ct);
    sincosf(phi, &sp, &cp);
    R[0] = cp * ct; R[1] = -st;  R[2] = sp * ct;
    R[3] = cp * st; R[4] = ct;   R[5] = sp * st;
    R[6] = -sp;     R[7] = 0.0f; R[8] = cp;
}

// ---------------------------------------------------------------------------
// Kernel 1: per-node rotation matrix + canonical velocity
// ---------------------------------------------------------------------------
__global__ void node_pre_kernel(const float* __restrict__ inp) {
    int idx = blockIdx.x * 128 + threadIdx.x;
    if (idx >= NODES) return;
    const float* v = inp + (size_t)idx * 6 + 3;
    float vx = v[0], vy = v[1], vz = v[2];
    float R[9];
    vel_to_R(vx, vy, vz, R);
#pragma unroll
    for (int i = 0; i < 9; i++) g_R[idx * 9 + i] = R[i];
    g_cv[idx * 3 + 0] = R[0] * vx + R[3] * vy + R[6] * vz;
    g_cv[idx * 3 + 1] = R[1] * vx + R[4] * vy + R[7] * vz;
    g_cv[idx * 3 + 2] = R[2] * vx + R[5] * vy + R[8] * vz;
}

// ---------------------------------------------------------------------------
// Kernel 2: edge aggregation via mma.sync f16 2-split (A split, B single).
// Per warp: 32 channels (2 m-tiles). Per node: 13 n-tiles x 4 MMAs.
// Packed f32x2 silu epilogue with Sum(m) + Sum(m*tanh m) identity.
// ---------------------------------------------------------------------------
#define EBLOCKS 1280
#define ENODES_PER_BLK 10
#define FSTRIDE 9             // u32 words per edge row (8 f16x2 + 1 pad)

__global__ __launch_bounds__(128) void edge_hmma_kernel(
    const float* __restrict__ inp,
    const float* __restrict__ W1,
    const float* __restrict__ b1)
{
    __shared__ uint32_t feat[104 * FSTRIDE];

    int t = threadIdx.x;
    int w = t >> 5;
    int lane = t & 31;
    int g = lane >> 2;        // 0..7
    int t4 = lane & 3;        // 0..3

    // zero feature array once (covers k-pad word and edge rows 99..103)
    for (int i = t; i < 104 * FSTRIDE; i += 128) feat[i] = 0u;

    // ---- A fragments: 0.5*W1^T in fp16 hi/lo split (rows=channels, k pad 0)
    uint32_t Ahi[2][4], Alo[2][4];
#pragma unroll
    for (int mt = 0; mt < 2; mt++) {
        int r0 = w * 32 + mt * 16 + g;
        int r1 = r0 + 8;
        int c0 = 2 * t4;
        int c2 = c0 + 8;
        float v00 = 0.5f * W1[c0 * HH + r0];
        float v01 = 0.5f * W1[(c0 + 1) * HH + r0];
        float v10 = 0.5f * W1[c0 * HH + r1];
        float v11 = 0.5f * W1[(c0 + 1) * HH + r1];
        float v02 = (c2     < 12) ? 0.5f * W1[c2 * HH + r0]       : 0.0f;
        float v03 = (c2 + 1 < 12) ? 0.5f * W1[(c2 + 1) * HH + r0] : 0.0f;
        float v12 = (c2     < 12) ? 0.5f * W1[c2 * HH + r1]       : 0.0f;
        float v13 = (c2 + 1 < 12) ? 0.5f * W1[(c2 + 1) * HH + r1] : 0.0f;
        uint32_t h0, l0, h1, l1;
        splith(v00, h0, l0); splith(v01, h1, l1);
        Ahi[mt][0] = pkh(h0, h1); Alo[mt][0] = pkh(l0, l1);
        splith(v10, h0, l0); splith(v11, h1, l1);
        Ahi[mt][1] = pkh(h0, h1); Alo[mt][1] = pkh(l0, l1);
        splith(v02, h0, l0); splith(v03, h1, l1);
        Ahi[mt][2] = pkh(h0, h1); Alo[mt][2] = pkh(l0, l1);
        splith(v12, h0, l0); splith(v13, h1, l1);
        Ahi[mt][3] = pkh(h0, h1); Alo[mt][3] = pkh(l0, l1);
    }

    // base-term constants for the 4 owned channel rows: g, g+8, g+16, g+24
    float b0h[4], w15[4], w16[4], w17[4];
#pragma unroll
    for (int i = 0; i < 4; i++) {
        int ch = w * 32 + (i >> 1) * 16 + (i & 1) * 8 + g;   // mt-major order
        b0h[i] = 0.5f * b1[ch];
        w15[i] = 0.5f * W1[15 * HH + ch];
        w16[i] = 0.5f * W1[16 * HH + ch];
        w17[i] = 0.5f * W1[17 * HH + ch];
    }
    // packed mask for the peeled tile (edges 96..103, keep <99)
    u64 mask2 = pack2((96 + 2 * t4 < 99) ? 1.0f : 0.0f,
                      (97 + 2 * t4 < 99) ? 1.0f : 0.0f);
    __syncthreads();

    for (int ni = 0; ni < ENODES_PER_BLK; ni++) {
        int node = blockIdx.x * ENODES_PER_BLK + ni;

        // ---- build edge features (threads 0..98) -> single fp16 smem ----
        if (t < NN - 1) {
            int r_local = node % NN;
            int s = t + (t >= r_local ? 1 : 0);
            int node_s = node - r_local + s;
            const float* xj = inp + (size_t)node_s * 6;
            const float* xi = inp + (size_t)node * 6;
            float Rr[9], Rs[9];
#pragma unroll
            for (int i = 0; i < 9; i++) { Rr[i] = g_R[node * 9 + i]; Rs[i] = g_R[node_s * 9 + i]; }

            float rel0 = xj[0] - xi[0], rel1 = xj[1] - xi[1], rel2 = xj[2] - xi[2];
            float rr0 = Rr[0] * rel0 + Rr[3] * rel1 + Rr[6] * rel2;
            float rr1 = Rr[1] * rel0 + Rr[4] * rel1 + Rr[7] * rel2;
            float rr2 = Rr[2] * rel0 + Rr[5] * rel1 + Rr[8] * rel2;
            float ro00 = Rr[0] * Rs[0] + Rr[3] * Rs[3] + Rr[6] * Rs[6];
            float ro10 = Rr[1] * Rs[0] + Rr[4] * Rs[3] + Rr[7] * Rs[6];
            float ro20 = Rr[2] * Rs[0] + Rr[5] * Rs[3] + Rr[8] * Rs[6];
            float ro21 = Rr[2] * Rs[1] + Rr[5] * Rs[4] + Rr[8] * Rs[7];
            float ro22 = Rr[2] * Rs[2] + Rr[5] * Rs[5] + Rr[8] * Rs[8];

            float f[12];
            f[0] = rr0; f[1] = rr1; f[2] = rr2;
            f[3] = atan2f(ro10, ro00) * (1.0f / PI_F);
            float sa = fminf(fmaxf(-ro20, -1.0f), 1.0f);
            f[4] = asinf(sa) * (1.0f / PI_F);
            f[5] = atan2f(ro21, ro22) * (1.0f / PI_F);
            f[6] = sqrtf(rel0 * rel0 + rel1 * rel1 + rel2 * rel2);
            f[7] = atan2f(rr1, rr0);
            float rho_e = sqrtf(rr0 * rr0 + rr1 * rr1 + rr2 * rr2);
            float cc = rr2 / (rho_e + EPS_F);
            cc = fminf(fmaxf(cc, -1.0f), 1.0f);
            f[8] = acosf(cc);
            float vj0 = xj[3], vj1 = xj[4], vj2 = xj[5];
            f[9]  = Rr[0] * vj0 + Rr[3] * vj1 + Rr[6] * vj2;
            f[10] = Rr[1] * vj0 + Rr[4] * vj1 + Rr[7] * vj2;
            f[11] = Rr[2] * vj0 + Rr[5] * vj1 + Rr[8] * vj2;

            int rb = t * FSTRIDE;
#pragma unroll
            for (int k2 = 0; k2 < 6; k2++)
                feat[rb + k2] = f16x2_pack(f[2 * k2], f[2 * k2 + 1]);
        }
        __syncthreads();

        // ---- per-node base (packed) ----
        float cv0 = g_cv[node * 3], cv1 = g_cv[node * 3 + 1], cv2 = g_cv[node * 3 + 2];
        u64 base2[4];
#pragma unroll
        for (int i = 0; i < 4; i++) {
            float b = fmaf(cv2, w17[i], fmaf(cv1, w16[i], fmaf(cv0, w15[i], b0h[i])));
            base2[i] = pack2(b, b);
        }

        u64 accM[4] = {0, 0, 0, 0}, accT[4] = {0, 0, 0, 0};

        // ---- 12 full n-tiles ----
#pragma unroll 1
        for (int nt = 0; nt < 12; nt++) {
            const uint32_t* fp = feat + (nt * 8 + g) * FSTRIDE;
            uint32_t b0 = fp[t4], b1v = fp[4 + t4];

            float d0[4] = {0.f, 0.f, 0.f, 0.f};
            float d1[4] = {0.f, 0.f, 0.f, 0.f};
            mma_f16(d0, Ahi[0], b0, b1v);
            mma_f16(d0, Alo[0], b0, b1v);
            mma_f16(d1, Ahi[1], b0, b1v);
            mma_f16(d1, Alo[1], b0, b1v);

            u64 m0 = add2(packu(__float_as_uint(d0[0]), __float_as_uint(d0[1])), base2[0]);
            u64 m1 = add2(packu(__float_as_uint(d0[2]), __float_as_uint(d0[3])), base2[1]);
            u64 m2 = add2(packu(__float_as_uint(d1[0]), __float_as_uint(d1[1])), base2[2]);
            u64 m3 = add2(packu(__float_as_uint(d1[2]), __float_as_uint(d1[3])), base2[3]);
            float a, b;
            unpack2(m0, a, b); u64 t0 = pack2(tanh_fast(a), tanh_fast(b));
            unpack2(m1, a, b); u64 t1 = pack2(tanh_fast(a), tanh_fast(b));
            unpack2(m2, a, b); u64 t2 = pack2(tanh_fast(a), tanh_fast(b));
            unpack2(m3, a, b); u64 t3 = pack2(tanh_fast(a), tanh_fast(b));
            accM[0] = add2(accM[0], m0); accT[0] = fma2(m0, t0, accT[0]);
            accM[1] = add2(accM[1], m1); accT[1] = fma2(m1, t1, accT[1]);
            accM[2] = add2(accM[2], m2); accT[2] = fma2(m2, t2, accT[2]);
            accM[3] = add2(accM[3], m3); accT[3] = fma2(m3, t3, accT[3]);
        }
        // ---- peeled tile 12 (edges 96..98 real) ----
        {
            const uint32_t* fp = feat + (12 * 8 + g) * FSTRIDE;
            uint32_t b0 = fp[t4], b1v = fp[4 + t4];
            float d0[4] = {0.f, 0.f, 0.f, 0.f};
            float d1[4] = {0.f, 0.f, 0.f, 0.f};
            mma_f16(d0, Ahi[0], b0, b1v);
            mma_f16(d0, Alo[0], b0, b1v);
            mma_f16(d1, Ahi[1], b0, b1v);
            mma_f16(d1, Alo[1], b0, b1v);
            u64 m0 = mul2(add2(packu(__float_as_uint(d0[0]), __float_as_uint(d0[1])), base2[0]), mask2);
            u64 m1 = mul2(add2(packu(__float_as_uint(d0[2]), __float_as_uint(d0[3])), base2[1]), mask2);
            u64 m2 = mul2(add2(packu(__float_as_uint(d1[0]), __float_as_uint(d1[1])), base2[2]), mask2);
            u64 m3 = mul2(add2(packu(__float_as_uint(d1[2]), __float_as_uint(d1[3])), base2[3]), mask2);
            float a, b;
            unpack2(m0, a, b); u64 t0 = pack2(tanh_fast(a), tanh_fast(b));
            unpack2(m1, a, b); u64 t1 = pack2(tanh_fast(a), tanh_fast(b));
            unpack2(m2, a, b); u64 t2 = pack2(tanh_fast(a), tanh_fast(b));
            unpack2(m3, a, b); u64 t3 = pack2(tanh_fast(a), tanh_fast(b));
            accM[0] = add2(accM[0], m0); accT[0] = fma2(m0, t0, accT[0]);
            accM[1] = add2(accM[1], m1); accT[1] = fma2(m1, t1, accT[1]);
            accM[2] = add2(accM[2], m2); accT[2] = fma2(m2, t2, accT[2]);
            accM[3] = add2(accM[3], m3); accT[3] = fma2(m3, t3, accT[3]);
        }

        // ---- reduce across the 4 lanes of each row-group, store ----
        float acc[4];
#pragma unroll
        for (int i = 0; i < 4; i++) {
            float ml, mh, tl, th;
            unpack2(accM[i], ml, mh);
            unpack2(accT[i], tl, th);
            acc[i] = ml + mh + tl + th;
            acc[i] += __shfl_xor_sync(0xffffffffu, acc[i], 1);
            acc[i] += __shfl_xor_sync(0xffffffffu, acc[i], 2);
        }
        if (t4 == 0) {
            float* hp = &g_hacc[(size_t)node * HH + w * 32 + g];
            hp[0]  = acc[0];   // mt0, row g
            hp[8]  = acc[1];   // mt0, row g+8
            hp[16] = acc[2];   // mt1, row g+16
            hp[24] = acc[3];   // mt1, row g+24
        }
        __syncthreads();
    }
}

// ---------------------------------------------------------------------------
// Kernel 3: register-tiled GEMM MLP (unchanged, proven)
// ---------------------------------------------------------------------------
#define MLP_BLOCKS 134
#define MLP_THREADS 384
#define NT 96
#define OFF_WT  0
#define OFF_A   16384
#define OFF_B   28672
#define OFF_W5T 40960
#define OFF_WR  41728
#define OFF_B2R 42112
#define OFF_B3  42240
#define OFF_B4  42368
#define OFF_B5  42496
#define SMEM_FL 42504

__device__ __forceinline__ int a_fidx(int n, int k) {
    return (n * 64 + ((k >> 1) ^ ((n >> 3) & 3))) * 2 + (k & 1);
}

template <int MODE>
__device__ __forceinline__ void gemm_layer(
    const u64* __restrict__ Ain, float* __restrict__ Bout,
    const u64* __restrict__ Wt, const float* __restrict__ bias,
    int n0, const float* __restrict__ wrS)
{
    int t = threadIdx.x;
    int warp = t >> 5, lane = t & 31;
    int wr = warp >> 2, wc = warp & 3;
    int ng = lane >> 3, cg = lane & 7;
    int nb = wr * 32 + ng * 8;
    int cb = wc * 32 + cg * 4;
    int swzx = (nb >> 3) & 3;
    int swzw = cg;

    const u64* Ap = Ain + nb * 64;
    const u64* Wp = Wt + cb * 64;

    u64 acc[8][4];
#pragma unroll
    for (int i = 0; i < 8; i++)
#pragma unroll
        for (int j = 0; j < 4; j++) acc[i][j] = 0ull;

#pragma unroll 4
    for (int kp = 0; kp < 64; kp++) {
        int ox = kp ^ swzx;
        int ow = kp ^ swzw;
        u64 xr[8], wv[4];
#pragma unroll
        for (int i = 0; i < 8; i++) xr[i] = Ap[i * 64 + ox];
#pragma unroll
        for (int j = 0; j < 4; j++) wv[j] = Wp[j * 64 + ow];
#pragma unroll
        for (int i = 0; i < 8; i++)
#pragma unroll
            for (int j = 0; j < 4; j++) acc[i][j] = fma2(xr[i], wv[j], acc[i][j]);
    }

#pragma unroll
    for (int i = 0; i < 8; i++) {
        int n = nb + i;
        int sw = (n >> 3) & 3;
        float cvx = 0.f, cvy = 0.f, cvz = 0.f;
        if (MODE == 0) {
            int gn = n0 + n;
            cvx = g_cv[gn * 3 + 0]; cvy = g_cv[gn * 3 + 1]; cvz = g_cv[gn * 3 + 2];
        }
#pragma unroll
        for (int j = 0; j < 4; j++) {
            int c = cb + j;
            float lo, hi;
            unpack2(acc[i][j], lo, hi);
            float s = lo + hi + bias[c];
            if (MODE == 0) s += cvx * wrS[c] + cvy * wrS[128 + c] + cvz * wrS[256 + c];
            else s = fmaxf(s, 0.0f);
            Bout[(n * 64 + ((c >> 1) ^ sw)) * 2 + (c & 1)] = s;
        }
    }
}

__global__ __launch_bounds__(MLP_THREADS, 1) void node_mlp_kernel(
    const float* __restrict__ inp,
    const float* __restrict__ W2, const float* __restrict__ b2,
    const float* __restrict__ Wr, const float* __restrict__ br,
    const float* __restrict__ W3, const float* __restrict__ b3,
    const float* __restrict__ W4, const float* __restrict__ b4,
    const float* __restrict__ W5, const float* __restrict__ b5,
    float* __restrict__ out)
{
    extern __shared__ float sm[];
    int t = threadIdx.x;
    int n0 = blockIdx.x * NT;
    const float inv99 = 1.0f / 99.0f;

    for (int idx = t; idx < NT * 128; idx += MLP_THREADS) {
        int n = idx >> 7, k = idx & 127;
        sm[OFF_A + a_fidx(n, k)] = g_hacc[(size_t)(n0 + n) * 128 + k] * inv99;
    }
    for (int idx = t; idx < 768; idx += MLP_THREADS) {
        int k = idx / 6, j = idx % 6;
        sm[OFF_W5T + j * 128 + k] = W5[idx];
    }
    for (int idx = t; idx < 384; idx += MLP_THREADS) sm[OFF_WR + idx] = Wr[384 + idx];
    if (t < 128) {
        sm[OFF_B2R + t] = b2[t] + br[t];
        sm[OFF_B3 + t] = b3[t];
        sm[OFF_B4 + t] = b4[t];
    }
    if (t < 6) sm[OFF_B5 + t] = b5[t];

    u64* A64 = (u64*)(sm + OFF_A);
    u64* B64 = (u64*)(sm + OFF_B);
    u64* Wt64 = (u64*)(sm + OFF_WT);

    for (int idx = t; idx < 16384; idx += MLP_THREADS) {
        int k = idx >> 7, c = idx & 127;
        sm[OFF_WT + (c * 64 + ((k >> 1) ^ ((c >> 2) & 7))) * 2 + (k & 1)] = W2[idx];
    }
    __syncthreads();
    gemm_layer<0>(A64, sm + OFF_B, Wt64, sm + OFF_B2R, n0, sm + OFF_WR);
    __syncthreads();

    for (int idx = t; idx < 16384; idx += MLP_THREADS) {
        int k = idx >> 7, c = idx & 127;
        sm[OFF_WT + (c * 64 + ((k >> 1) ^ ((c >> 2) & 7))) * 2 + (k & 1)] = W3[idx];
    }
    __syncthreads();
    gemm_layer<1>(B64, sm + OFF_A, Wt64, sm + OFF_B3, n0, nullptr);
    __syncthreads();

    for (int idx = t; idx < 16384; idx += MLP_THREADS) {
        int k = idx >> 7, c = idx & 127;
        sm[OFF_WT + (c * 64 + ((k >> 1) ^ ((c >> 2) & 7))) * 2 + (k & 1)] = W4[idx];
    }
    __syncthreads();
    gemm_layer<1>(A64, sm + OFF_B, Wt64, sm + OFF_B4, n0, nullptr);
    __syncthreads();

    if (t < NT) {
        int gnode = n0 + t;
        if (gnode < NODES) {
            int sw = (t >> 3) & 3;
            const u64* Pp = B64 + t * 64;
            u64 sj2[6];
#pragma unroll
            for (int j = 0; j < 6; j++) sj2[j] = 0ull;
#pragma unroll 8
            for (int kp = 0; kp < 64; kp++) {
                u64 x2 = Pp[kp ^ sw];
#pragma unroll
                for (int j = 0; j < 6; j++) {
                    u64 w2 = *(const u64*)&sm[OFF_W5T + j * 128 + 2 * kp];
                    sj2[j] = fma2(x2, w2, sj2[j]);
                }
            }
            float pred[6];
#pragma unroll
            for (int j = 0; j < 6; j++) {
                float lo, hi;
                unpack2(sj2[j], lo, hi);
                pred[j] = lo + hi + sm[OFF_B5 + j];
            }
            const float* R = g_R + (size_t)gnode * 9;
            float Rl[9];
#pragma unroll
            for (int i = 0; i < 9; i++) Rl[i] = R[i];
            const float* xin = inp + (size_t)gnode * 6;
            float* xout = out + (size_t)gnode * 6;
#pragma unroll
            for (int j = 0; j < 6; j++) {
                int i = j % 3, off = (j / 3) * 3;
                float gl = Rl[i * 3 + 0] * pred[off + 0]
                         + Rl[i * 3 + 1] * pred[off + 1]
                         + Rl[i * 3 + 2] * pred[off + 2];
                xout[j] = xin[j] + gl;
            }
        }
    }
}

// ---------------------------------------------------------------------------
extern "C" void kernel_launch(void* const* d_in, const int* in_sizes, int n_in,
                              void* d_out, int out_size)
{
    const float* inp = (const float*)d_in[0];
    const float* W1  = (const float*)d_in[1];
    const float* b1  = (const float*)d_in[2];
    const float* W2  = (const float*)d_in[3];
    const float* b2  = (const float*)d_in[4];
    const float* Wr  = (const float*)d_in[5];
    const float* br  = (const float*)d_in[6];
    const float* W3  = (const float*)d_in[7];
    const float* b3  = (const float*)d_in[8];
    const float* W4  = (const float*)d_in[9];
    const float* b4  = (const float*)d_in[10];
    const float* W5  = (const float*)d_in[11];
    const float* b5  = (const float*)d_in[12];
    float* out = (float*)d_out;

    const int SMEM3 = SMEM_FL * 4;
    cudaFuncSetAttribute(node_mlp_kernel,
                         cudaFuncAttributeMaxDynamicSharedMemorySize, SMEM3);

    node_pre_kernel<<<NODES / 128, 128>>>(inp);
    edge_hmma_kernel<<<EBLOCKS, 128>>>(inp, W1, b1);
    node_mlp_kernel<<<MLP_BLOCKS, MLP_THREADS, SMEM3>>>(inp, W2, b2, Wr, br,
                                                        W3, b3, W4, b4, W5, b5, out);
}

// round 13
// speedup vs baseline: 3.7339x; 1.0856x over previous
#include <cuda_runtime.h>
#include <cuda_fp16.h>
#include <math.h>
#include <stdint.h>

#define BB 128
#define NN 100
#define HH 128
#define NODES (BB*NN)          // 12800
#define NODES_PAD 12864
#define PI_F 3.14159265358979323846f
#define EPS_F 1e-7f

__device__ float g_R[NODES_PAD * 9];
__device__ float g_cv[NODES_PAD * 3];
__device__ float g_hacc[NODES_PAD * HH];

typedef unsigned long long u64;

// ---- packed f32x2 helpers -------------------------------------------------
__device__ __forceinline__ u64 fma2(u64 a, u64 b, u64 c) {
    u64 d;
    asm("fma.rn.f32x2 %0, %1, %2, %3;" : "=l"(d) : "l"(a), "l"(b), "l"(c));
    return d;
}
__device__ __forceinline__ u64 add2(u64 a, u64 b) {
    u64 d; asm("add.rn.f32x2 %0, %1, %2;" : "=l"(d) : "l"(a), "l"(b)); return d;
}
__device__ __forceinline__ u64 mul2(u64 a, u64 b) {
    u64 d; asm("mul.rn.f32x2 %0, %1, %2;" : "=l"(d) : "l"(a), "l"(b)); return d;
}
__device__ __forceinline__ u64 pack2(float lo, float hi) {
    u64 d; asm("mov.b64 %0, {%1, %2};" : "=l"(d) : "f"(lo), "f"(hi)); return d;
}
__device__ __forceinline__ u64 packu(uint32_t a, uint32_t b) {
    u64 d; asm("mov.b64 %0, {%1, %2};" : "=l"(d) : "r"(a), "r"(b)); return d;
}
__device__ __forceinline__ void unpack2(u64 v, float& lo, float& hi) {
    asm("mov.b64 {%0, %1}, %2;" : "=f"(lo), "=f"(hi) : "l"(v));
}
__device__ __forceinline__ float tanh_fast(float x) {
    float r; asm("tanh.approx.f32 %0, %1;" : "=f"(r) : "f"(x)); return r;
}
// pack two f32 -> f16x2 (lo in low half)
__device__ __forceinline__ uint32_t f16x2_pack(float lo, float hi) {
    uint32_t r;
    asm("cvt.rn.f16x2.f32 %0, %1, %2;" : "=r"(r) : "f"(hi), "f"(lo));
    return r;
}

// mma.sync m16n8k16 row.col f16 -> f32 accumulate
__device__ __forceinline__ void mma_f16(float* d, const uint32_t* a,
                                        uint32_t b0, uint32_t b1) {
    asm volatile(
        "mma.sync.aligned.m16n8k16.row.col.f32.f16.f16.f32 "
        "{%0,%1,%2,%3}, {%4,%5,%6,%7}, {%8,%9}, {%0,%1,%2,%3};"
        : "+f"(d[0]), "+f"(d[1]), "+f"(d[2]), "+f"(d[3])
        : "r"(a[0]), "r"(a[1]), "r"(a[2]), "r"(a[3]), "r"(b0), "r"(b1));
}

__device__ __forceinline__ void vel_to_R(float vx, float vy, float vz, float* R) {
    float rho = sqrtf(vx * vx + vy * vy + vz * vz);
    float theta = atan2f(vy, vx);
    if (theta < 0.0f) theta += 2.0f * PI_F;
    float c = vz / (rho + EPS_F);
    c = fminf(fmaxf(c, -1.0f), 1.0f);
    float phi = acosf(c);
    float st, ct, sp, cp;
    sincosf(theta, &st, &ct);
    sincosf(phi, &sp, &cp);
    R[0] = cp * ct; R[1] = -st;  R[2] = sp * ct;
    R[3] = cp * st; R[4] = ct;   R[5] = sp * st;
    R[6] = -sp;     R[7] = 0.0f; R[8] = cp;
}

// ---------------------------------------------------------------------------
// Kernel 1: per-node rotation matrix + canonical velocity
// ---------------------------------------------------------------------------
__global__ void node_pre_kernel(const float* __restrict__ inp) {
    int idx = blockIdx.x * 128 + threadIdx.x;
    if (idx >= NODES) return;
    const float* v = inp + (size_t)idx * 6 + 3;
    float vx = v[0], vy = v[1], vz = v[2];
    float R[9];
    vel_to_R(vx, vy, vz, R);
#pragma unroll
    for (int i = 0; i < 9; i++) g_R[idx * 9 + i] = R[i];
    g_cv[idx * 3 + 0] = R[0] * vx + R[3] * vy + R[6] * vz;
    g_cv[idx * 3 + 1] = R[1] * vx + R[4] * vy + R[7] * vz;
    g_cv[idx * 3 + 2] = R[2] * vx + R[5] * vy + R[8] * vz;
}

// ---------------------------------------------------------------------------
// Kernel 2: edge aggregation via mma.sync f16 (single precision-level).
// Per warp: 32 channels (2 m-tiles). Per node: 13 n-tiles x 2 MMAs.
// Packed f32x2 silu epilogue with Sum(m) + Sum(m*tanh m) identity.
// ---------------------------------------------------------------------------
#define EBLOCKS 1280
#define ENODES_PER_BLK 10
#define FSTRIDE 9             // u32 words per edge row (8 f16x2 + 1 pad)

__global__ __launch_bounds__(128) void edge_hmma_kernel(
    const float* __restrict__ inp,
    const float* __restrict__ W1,
    const float* __restrict__ b1)
{
    __shared__ uint32_t feat[104 * FSTRIDE];

    int t = threadIdx.x;
    int w = t >> 5;
    int lane = t & 31;
    int g = lane >> 2;        // 0..7
    int t4 = lane & 3;        // 0..3

    // zero feature array once (covers k-pad word and edge rows 99..103)
    for (int i = t; i < 104 * FSTRIDE; i += 128) feat[i] = 0u;

    // ---- A fragments: 0.5*W1^T in single fp16 (rows=channels, k pad 0)
    uint32_t Ah[2][4];
#pragma unroll
    for (int mt = 0; mt < 2; mt++) {
        int r0 = w * 32 + mt * 16 + g;
        int r1 = r0 + 8;
        int c0 = 2 * t4;
        int c2 = c0 + 8;
        float v00 = 0.5f * W1[c0 * HH + r0];
        float v01 = 0.5f * W1[(c0 + 1) * HH + r0];
        float v10 = 0.5f * W1[c0 * HH + r1];
        float v11 = 0.5f * W1[(c0 + 1) * HH + r1];
        float v02 = (c2     < 12) ? 0.5f * W1[c2 * HH + r0]       : 0.0f;
        float v03 = (c2 + 1 < 12) ? 0.5f * W1[(c2 + 1) * HH + r0] : 0.0f;
        float v12 = (c2     < 12) ? 0.5f * W1[c2 * HH + r1]       : 0.0f;
        float v13 = (c2 + 1 < 12) ? 0.5f * W1[(c2 + 1) * HH + r1] : 0.0f;
        Ah[mt][0] = f16x2_pack(v00, v01);
        Ah[mt][1] = f16x2_pack(v10, v11);
        Ah[mt][2] = f16x2_pack(v02, v03);
        Ah[mt][3] = f16x2_pack(v12, v13);
    }

    // base-term constants for the 4 owned channel rows (mt-major order)
    float b0h[4], w15[4], w16[4], w17[4];
#pragma unroll
    for (int i = 0; i < 4; i++) {
        int ch = w * 32 + (i >> 1) * 16 + (i & 1) * 8 + g;
        b0h[i] = 0.5f * b1[ch];
        w15[i] = 0.5f * W1[15 * HH + ch];
        w16[i] = 0.5f * W1[16 * HH + ch];
        w17[i] = 0.5f * W1[17 * HH + ch];
    }
    // packed mask for the peeled tile (edges 96..103, keep <99)
    u64 mask2 = pack2((96 + 2 * t4 < 99) ? 1.0f : 0.0f,
                      (97 + 2 * t4 < 99) ? 1.0f : 0.0f);
    __syncthreads();

    for (int ni = 0; ni < ENODES_PER_BLK; ni++) {
        int node = blockIdx.x * ENODES_PER_BLK + ni;

        // ---- build edge features (threads 0..98) -> single fp16 smem ----
        if (t < NN - 1) {
            int r_local = node % NN;
            int s = t + (t >= r_local ? 1 : 0);
            int node_s = node - r_local + s;
            const float* xj = inp + (size_t)node_s * 6;
            const float* xi = inp + (size_t)node * 6;
            float Rr[9], Rs[9];
#pragma unroll
            for (int i = 0; i < 9; i++) { Rr[i] = g_R[node * 9 + i]; Rs[i] = g_R[node_s * 9 + i]; }

            float rel0 = xj[0] - xi[0], rel1 = xj[1] - xi[1], rel2 = xj[2] - xi[2];
            float rr0 = Rr[0] * rel0 + Rr[3] * rel1 + Rr[6] * rel2;
            float rr1 = Rr[1] * rel0 + Rr[4] * rel1 + Rr[7] * rel2;
            float rr2 = Rr[2] * rel0 + Rr[5] * rel1 + Rr[8] * rel2;
            float ro00 = Rr[0] * Rs[0] + Rr[3] * Rs[3] + Rr[6] * Rs[6];
            float ro10 = Rr[1] * Rs[0] + Rr[4] * Rs[3] + Rr[7] * Rs[6];
            float ro20 = Rr[2] * Rs[0] + Rr[5] * Rs[3] + Rr[8] * Rs[6];
            float ro21 = Rr[2] * Rs[1] + Rr[5] * Rs[4] + Rr[8] * Rs[7];
            float ro22 = Rr[2] * Rs[2] + Rr[5] * Rs[5] + Rr[8] * Rs[8];

            float f[12];
            f[0] = rr0; f[1] = rr1; f[2] = rr2;
            f[3] = atan2f(ro10, ro00) * (1.0f / PI_F);
            float sa = fminf(fmaxf(-ro20, -1.0f), 1.0f);
            f[4] = asinf(sa) * (1.0f / PI_F);
            f[5] = atan2f(ro21, ro22) * (1.0f / PI_F);
            f[6] = sqrtf(rel0 * rel0 + rel1 * rel1 + rel2 * rel2);
            f[7] = atan2f(rr1, rr0);
            float rho_e = sqrtf(rr0 * rr0 + rr1 * rr1 + rr2 * rr2);
            float cc = rr2 / (rho_e + EPS_F);
            cc = fminf(fmaxf(cc, -1.0f), 1.0f);
            f[8] = acosf(cc);
            float vj0 = xj[3], vj1 = xj[4], vj2 = xj[5];
            f[9]  = Rr[0] * vj0 + Rr[3] * vj1 + Rr[6] * vj2;
            f[10] = Rr[1] * vj0 + Rr[4] * vj1 + Rr[7] * vj2;
            f[11] = Rr[2] * vj0 + Rr[5] * vj1 + Rr[8] * vj2;

            int rb = t * FSTRIDE;
#pragma unroll
            for (int k2 = 0; k2 < 6; k2++)
                feat[rb + k2] = f16x2_pack(f[2 * k2], f[2 * k2 + 1]);
        }
        __syncthreads();

        // ---- per-node base (packed) ----
        float cv0 = g_cv[node * 3], cv1 = g_cv[node * 3 + 1], cv2 = g_cv[node * 3 + 2];
        u64 base2[4];
#pragma unroll
        for (int i = 0; i < 4; i++) {
            float b = fmaf(cv2, w17[i], fmaf(cv1, w16[i], fmaf(cv0, w15[i], b0h[i])));
            base2[i] = pack2(b, b);
        }

        u64 accM[4] = {0, 0, 0, 0}, accT[4] = {0, 0, 0, 0};

        // ---- 12 full n-tiles ----
#pragma unroll 1
        for (int nt = 0; nt < 12; nt++) {
            const uint32_t* fp = feat + (nt * 8 + g) * FSTRIDE;
            uint32_t b0 = fp[t4], b1v = fp[4 + t4];

            float d0[4] = {0.f, 0.f, 0.f, 0.f};
            float d1[4] = {0.f, 0.f, 0.f, 0.f};
            mma_f16(d0, Ah[0], b0, b1v);
            mma_f16(d1, Ah[1], b0, b1v);

            u64 m0 = add2(packu(__float_as_uint(d0[0]), __float_as_uint(d0[1])), base2[0]);
            u64 m1 = add2(packu(__float_as_uint(d0[2]), __float_as_uint(d0[3])), base2[1]);
            u64 m2 = add2(packu(__float_as_uint(d1[0]), __float_as_uint(d1[1])), base2[2]);
            u64 m3 = add2(packu(__float_as_uint(d1[2]), __float_as_uint(d1[3])), base2[3]);
            float a, b;
            unpack2(m0, a, b); u64 t0 = pack2(tanh_fast(a), tanh_fast(b));
            unpack2(m1, a, b); u64 t1 = pack2(tanh_fast(a), tanh_fast(b));
            unpack2(m2, a, b); u64 t2 = pack2(tanh_fast(a), tanh_fast(b));
            unpack2(m3, a, b); u64 t3 = pack2(tanh_fast(a), tanh_fast(b));
            accM[0] = add2(accM[0], m0); accT[0] = fma2(m0, t0, accT[0]);
            accM[1] = add2(accM[1], m1); accT[1] = fma2(m1, t1, accT[1]);
            accM[2] = add2(accM[2], m2); accT[2] = fma2(m2, t2, accT[2]);
            accM[3] = add2(accM[3], m3); accT[3] = fma2(m3, t3, accT[3]);
        }
        // ---- peeled tile 12 (edges 96..98 real) ----
        {
            const uint32_t* fp = feat + (12 * 8 + g) * FSTRIDE;
            uint32_t b0 = fp[t4], b1v = fp[4 + t4];
            float d0[4] = {0.f, 0.f, 0.f, 0.f};
            float d1[4] = {0.f, 0.f, 0.f, 0.f};
            mma_f16(d0, Ah[0], b0, b1v);
            mma_f16(d1, Ah[1], b0, b1v);
            u64 m0 = mul2(add2(packu(__float_as_uint(d0[0]), __float_as_uint(d0[1])), base2[0]), mask2);
            u64 m1 = mul2(add2(packu(__float_as_uint(d0[2]), __float_as_uint(d0[3])), base2[1]), mask2);
            u64 m2 = mul2(add2(packu(__float_as_uint(d1[0]), __float_as_uint(d1[1])), base2[2]), mask2);
            u64 m3 = mul2(add2(packu(__float_as_uint(d1[2]), __float_as_uint(d1[3])), base2[3]), mask2);
            float a, b;
            unpack2(m0, a, b); u64 t0 = pack2(tanh_fast(a), tanh_fast(b));
            unpack2(m1, a, b); u64 t1 = pack2(tanh_fast(a), tanh_fast(b));
            unpack2(m2, a, b); u64 t2 = pack2(tanh_fast(a), tanh_fast(b));
            unpack2(m3, a, b); u64 t3 = pack2(tanh_fast(a), tanh_fast(b));
            accM[0] = add2(accM[0], m0); accT[0] = fma2(m0, t0, accT[0]);
            accM[1] = add2(accM[1], m1); accT[1] = fma2(m1, t1, accT[1]);
            accM[2] = add2(accM[2], m2); accT[2] = fma2(m2, t2, accT[2]);
            accM[3] = add2(accM[3], m3); accT[3] = fma2(m3, t3, accT[3]);
        }

        // ---- reduce across the 4 lanes of each row-group, store ----
        float acc[4];
#pragma unroll
        for (int i = 0; i < 4; i++) {
            float ml, mh, tl, th;
            unpack2(accM[i], ml, mh);
            unpack2(accT[i], tl, th);
            acc[i] = ml + mh + tl + th;
            acc[i] += __shfl_xor_sync(0xffffffffu, acc[i], 1);
            acc[i] += __shfl_xor_sync(0xffffffffu, acc[i], 2);
        }
        if (t4 == 0) {
            float* hp = &g_hacc[(size_t)node * HH + w * 32 + g];
            hp[0]  = acc[0];   // mt0, row g
            hp[8]  = acc[1];   // mt0, row g+8
            hp[16] = acc[2];   // mt1, row g+16
            hp[24] = acc[3];   // mt1, row g+24
        }
        __syncthreads();
    }
}

// ---------------------------------------------------------------------------
// Kernel 3: register-tiled GEMM MLP (unchanged, proven)
// ---------------------------------------------------------------------------
#define MLP_BLOCKS 134
#define MLP_THREADS 384
#define NT 96
#define OFF_WT  0
#define OFF_A   16384
#define OFF_B   28672
#define OFF_W5T 40960
#define OFF_WR  41728
#define OFF_B2R 42112
#define OFF_B3  42240
#define OFF_B4  42368
#define OFF_B5  42496
#define SMEM_FL 42504

__device__ __forceinline__ int a_fidx(int n, int k) {
    return (n * 64 + ((k >> 1) ^ ((n >> 3) & 3))) * 2 + (k & 1);
}

template <int MODE>
__device__ __forceinline__ void gemm_layer(
    const u64* __restrict__ Ain, float* __restrict__ Bout,
    const u64* __restrict__ Wt, const float* __restrict__ bias,
    int n0, const float* __restrict__ wrS)
{
    int t = threadIdx.x;
    int warp = t >> 5, lane = t & 31;
    int wr = warp >> 2, wc = warp & 3;
    int ng = lane >> 3, cg = lane & 7;
    int nb = wr * 32 + ng * 8;
    int cb = wc * 32 + cg * 4;
    int swzx = (nb >> 3) & 3;
    int swzw = cg;

    const u64* Ap = Ain + nb * 64;
    const u64* Wp = Wt + cb * 64;

    u64 acc[8][4];
#pragma unroll
    for (int i = 0; i < 8; i++)
#pragma unroll
        for (int j = 0; j < 4; j++) acc[i][j] = 0ull;

#pragma unroll 4
    for (int kp = 0; kp < 64; kp++) {
        int ox = kp ^ swzx;
        int ow = kp ^ swzw;
        u64 xr[8], wv[4];
#pragma unroll
        for (int i = 0; i < 8; i++) xr[i] = Ap[i * 64 + ox];
#pragma unroll
        for (int j = 0; j < 4; j++) wv[j] = Wp[j * 64 + ow];
#pragma unroll
        for (int i = 0; i < 8; i++)
#pragma unroll
            for (int j = 0; j < 4; j++) acc[i][j] = fma2(xr[i], wv[j], acc[i][j]);
    }

#pragma unroll
    for (int i = 0; i < 8; i++) {
        int n = nb + i;
        int sw = (n >> 3) & 3;
        float cvx = 0.f, cvy = 0.f, cvz = 0.f;
        if (MODE == 0) {
            int gn = n0 + n;
            cvx = g_cv[gn * 3 + 0]; cvy = g_cv[gn * 3 + 1]; cvz = g_cv[gn * 3 + 2];
        }
#pragma unroll
        for (int j = 0; j < 4; j++) {
            int c = cb + j;
            float lo, hi;
            unpack2(acc[i][j], lo, hi);
            float s = lo + hi + bias[c];
            if (MODE == 0) s += cvx * wrS[c] + cvy * wrS[128 + c] + cvz * wrS[256 + c];
            else s = fmaxf(s, 0.0f);
            Bout[(n * 64 + ((c >> 1) ^ sw)) * 2 + (c & 1)] = s;
        }
    }
}

__global__ __launch_bounds__(MLP_THREADS, 1) void node_mlp_kernel(
    const float* __restrict__ inp,
    const float* __restrict__ W2, const float* __restrict__ b2,
    const float* __restrict__ Wr, const float* __restrict__ br,
    const float* __restrict__ W3, const float* __restrict__ b3,
    const float* __restrict__ W4, const float* __restrict__ b4,
    const float* __restrict__ W5, const float* __restrict__ b5,
    float* __restrict__ out)
{
    extern __shared__ float sm[];
    int t = threadIdx.x;
    int n0 = blockIdx.x * NT;
    const float inv99 = 1.0f / 99.0f;

    for (int idx = t; idx < NT * 128; idx += MLP_THREADS) {
        int n = idx >> 7, k = idx & 127;
        sm[OFF_A + a_fidx(n, k)] = g_hacc[(size_t)(n0 + n) * 128 + k] * inv99;
    }
    for (int idx = t; idx < 768; idx += MLP_THREADS) {
        int k = idx / 6, j = idx % 6;
        sm[OFF_W5T + j * 128 + k] = W5[idx];
    }
    for (int idx = t; idx < 384; idx += MLP_THREADS) sm[OFF_WR + idx] = Wr[384 + idx];
    if (t < 128) {
        sm[OFF_B2R + t] = b2[t] + br[t];
        sm[OFF_B3 + t] = b3[t];
        sm[OFF_B4 + t] = b4[t];
    }
    if (t < 6) sm[OFF_B5 + t] = b5[t];

    u64* A64 = (u64*)(sm + OFF_A);
    u64* B64 = (u64*)(sm + OFF_B);
    u64* Wt64 = (u64*)(sm + OFF_WT);

    for (int idx = t; idx < 16384; idx += MLP_THREADS) {
        int k = idx >> 7, c = idx & 127;
        sm[OFF_WT + (c * 64 + ((k >> 1) ^ ((c >> 2) & 7))) * 2 + (k & 1)] = W2[idx];
    }
    __syncthreads();
    gemm_layer<0>(A64, sm + OFF_B, Wt64, sm + OFF_B2R, n0, sm + OFF_WR);
    __syncthreads();

    for (int idx = t; idx < 16384; idx += MLP_THREADS) {
        int k = idx >> 7, c = idx & 127;
        sm[OFF_WT + (c * 64 + ((k >> 1) ^ ((c >> 2) & 7))) * 2 + (k & 1)] = W3[idx];
    }
    __syncthreads();
    gemm_layer<1>(B64, sm + OFF_A, Wt64, sm + OFF_B3, n0, nullptr);
    __syncthreads();

    for (int idx = t; idx < 16384; idx += MLP_THREADS) {
        int k = idx >> 7, c = idx & 127;
        sm[OFF_WT + (c * 64 + ((k >> 1) ^ ((c >> 2) & 7))) * 2 + (k & 1)] = W4[idx];
    }
    __syncthreads();
    gemm_layer<1>(A64, sm + OFF_B, Wt64, sm + OFF_B4, n0, nullptr);
    __syncthreads();

    if (t < NT) {
        int gnode = n0 + t;
        if (gnode < NODES) {
            int sw = (t >> 3) & 3;
            const u64* Pp = B64 + t * 64;
            u64 sj2[6];
#pragma unroll
            for (int j = 0; j < 6; j++) sj2[j] = 0ull;
#pragma unroll 8
            for (int kp = 0; kp < 64; kp++) {
                u64 x2 = Pp[kp ^ sw];
#pragma unroll
                for (int j = 0; j < 6; j++) {
                    u64 w2 = *(const u64*)&sm[OFF_W5T + j * 128 + 2 * kp];
                    sj2[j] = fma2(x2, w2, sj2[j]);
                }
            }
            float pred[6];
#pragma unroll
            for (int j = 0; j < 6; j++) {
                float lo, hi;
                unpack2(sj2[j], lo, hi);
                pred[j] = lo + hi + sm[OFF_B5 + j];
            }
            const float* R = g_R + (size_t)gnode * 9;
            float Rl[9];
#pragma unroll
            for (int i = 0; i < 9; i++) Rl[i] = R[i];
            const float* xin = inp + (size_t)gnode * 6;
            float* xout = out + (size_t)gnode * 6;
#pragma unroll
            for (int j = 0; j < 6; j++) {
                int i = j % 3, off = (j / 3) * 3;
                float gl = Rl[i * 3 + 0] * pred[off + 0]
                         + Rl[i * 3 + 1] * pred[off + 1]
                         + Rl[i * 3 + 2] * pred[off + 2];
                xout[j] = xin[j] + gl;
            }
        }
    }
}

// ---------------------------------------------------------------------------
extern "C" void kernel_launch(void* const* d_in, const int* in_sizes, int n_in,
                              void* d_out, int out_size)
{
    const float* inp = (const float*)d_in[0];
    const float* W1  = (const float*)d_in[1];
    const float* b1  = (const float*)d_in[2];
    const float* W2  = (const float*)d_in[3];
    const float* b2  = (const float*)d_in[4];
    const float* Wr  = (const float*)d_in[5];
    const float* br  = (const float*)d_in[6];
    const float* W3  = (const float*)d_in[7];
    const float* b3  = (const float*)d_in[8];
    const float* W4  = (const float*)d_in[9];
    const float* b4  = (const float*)d_in[10];
    const float* W5  = (const float*)d_in[11];
    const float* b5  = (const float*)d_in[12];
    float* out = (float*)d_out;

    const int SMEM3 = SMEM_FL * 4;
    cudaFuncSetAttribute(node_mlp_kernel,
                         cudaFuncAttributeMaxDynamicSharedMemorySize, SMEM3);

    node_pre_kernel<<<NODES / 128, 128>>>(inp);
    edge_hmma_kernel<<<EBLOCKS, 128>>>(inp, W1, b1);
    node_mlp_kernel<<<MLP_BLOCKS, MLP_THREADS, SMEM3>>>(inp, W2, b2, Wr, br,
                                                        W3, b3, W4, b4, W5, b5, out);
}